// round 9
// baseline (speedup 1.0000x reference)
#include <cuda_runtime.h>
#include <cuda_bf16.h>
#include <math.h>

#define B_   32
#define T_   48
#define L_   400
#define H2_  512
#define E_   128
#define V_   50000
#define OOV_ 100
#define VEXT_ 50100
#define BT_  (B_*T_)

// ---------------- scratch (static device allocations; no cudaMalloc) ----------------
__device__ float g_Xe[BT_*H2_];
__device__ float g_Xd[BT_*H2_];
__device__ float g_att[BT_*L_];        // e -> temporal -> enc_att (in place)
__device__ float g_s[BT_*T_];          // normalized dec attention
__device__ float g_cat[BT_*3*H2_];     // [h | enc_ctx | dec_ctx]
__device__ float g_proj[BT_*E_];
__device__ float g_p[BT_];
__device__ float g_rsum[BT_];
__device__ float g_logits[(size_t)BT_*V_];            // holds exp(logits), 307 MB
__device__ __nv_bfloat16 g_A2[(size_t)BT_*3*E_];      // split A: [hi|hi|lo], (BT,384)
__device__ __nv_bfloat16 g_B2t[(size_t)V_*3*E_];      // split B^T: rows [hi;lo;hi], (V,384)

// ============ templated fp32 GEMM: C = A * op(B), TK=32, float4 loads ============
// 256 threads, 16x16 thread grid, microtile (TM/16)x(TN/16), register prefetch.
// Requires: K % 4 == 0 and N % 4 == 0 (true for all uses here).
template<int TMv, int TNv>
__global__ void __launch_bounds__(256) gemm_t(
    int M, int N, int K,
    const float* __restrict__ A, int lda, long long sA,
    const float* __restrict__ B, int ldb, long long sB, int transB,
    float* __restrict__ C, int ldc, long long sC)
{
    constexpr int TK = 32;
    constexpr int MR = TMv / 16;
    constexpr int NR = TNv / 16;
    constexpr int A4 = TMv * TK / (256 * 4);   // float4 loads per thread (A)
    constexpr int B4 = TNv * TK / (256 * 4);   // float4 loads per thread (B)
    __shared__ float As[TK][TMv];
    __shared__ float Bs[TK][TNv];

    int bz = blockIdx.z;
    A += (long long)bz * sA;
    B += (long long)bz * sB;
    C += (long long)bz * sC;
    int m0 = blockIdx.y * TMv;
    int n0 = blockIdx.x * TNv;
    int tid = threadIdx.x;
    int tx = tid & 15, ty = tid >> 4;
    float acc[MR][NR];
#pragma unroll
    for (int i = 0; i < MR; i++)
#pragma unroll
        for (int j = 0; j < NR; j++) acc[i][j] = 0.f;

    float4 ra[A4], rb[B4];

    auto ldA = [&](int kk) {
#pragma unroll
        for (int i = 0; i < A4; i++) {
            int f = tid + 256 * i;                 // 0 .. TMv*8-1
            int row = f >> 3, c = (f & 7) << 2;
            int gm = m0 + row, gk = kk + c;
            ra[i] = (gm < M && gk < K) ? *(const float4*)(A + (long long)gm * lda + gk)
                                       : make_float4(0.f, 0.f, 0.f, 0.f);
        }
    };
    auto ldB = [&](int kk) {
        if (transB) {
#pragma unroll
            for (int i = 0; i < B4; i++) {
                int f = tid + 256 * i;             // 0 .. TNv*8-1
                int row = f >> 3, c = (f & 7) << 2;
                int gn = n0 + row, gk = kk + c;
                rb[i] = (gn < N && gk < K) ? *(const float4*)(B + (long long)gn * ldb + gk)
                                           : make_float4(0.f, 0.f, 0.f, 0.f);
            }
        } else {
#pragma unroll
            for (int i = 0; i < B4; i++) {
                int f = tid + 256 * i;             // 0 .. 8*TNv-1
                int k = f / (TNv / 4);
                int n = (f % (TNv / 4)) * 4;
                int gk = kk + k, gn = n0 + n;
                rb[i] = (gk < K && gn < N) ? *(const float4*)(B + (long long)gk * ldb + gn)
                                           : make_float4(0.f, 0.f, 0.f, 0.f);
            }
        }
    };
    auto stA = [&]() {
#pragma unroll
        for (int i = 0; i < A4; i++) {
            int f = tid + 256 * i;
            int row = f >> 3, c = (f & 7) << 2;
            As[c+0][row] = ra[i].x; As[c+1][row] = ra[i].y;
            As[c+2][row] = ra[i].z; As[c+3][row] = ra[i].w;
        }
    };
    auto stB = [&](int tB) {
        if (tB) {
#pragma unroll
            for (int i = 0; i < B4; i++) {
                int f = tid + 256 * i;
                int row = f >> 3, c = (f & 7) << 2;
                Bs[c+0][row] = rb[i].x; Bs[c+1][row] = rb[i].y;
                Bs[c+2][row] = rb[i].z; Bs[c+3][row] = rb[i].w;
            }
        } else {
#pragma unroll
            for (int i = 0; i < B4; i++) {
                int f = tid + 256 * i;
                int k = f / (TNv / 4);
                int n = (f % (TNv / 4)) * 4;
                *(float4*)&Bs[k][n] = rb[i];
            }
        }
    };

    ldA(0); ldB(0);
    for (int kk = 0; kk < K; kk += TK) {
        stA(); stB(transB);
        __syncthreads();
        int kn = kk + TK;
        if (kn < K) { ldA(kn); ldB(kn); }
#pragma unroll
        for (int k = 0; k < TK; k++) {
            float a0[MR], b0[NR];
#pragma unroll
            for (int i = 0; i < MR; i++) a0[i] = As[k][ty*MR + i];
#pragma unroll
            for (int j = 0; j < NR; j++) b0[j] = Bs[k][tx*NR + j];
#pragma unroll
            for (int i = 0; i < MR; i++)
#pragma unroll
                for (int j = 0; j < NR; j++)
                    acc[i][j] = fmaf(a0[i], b0[j], acc[i][j]);
        }
        __syncthreads();
    }
#pragma unroll
    for (int i = 0; i < MR; i++) {
        int gm = m0 + ty*MR + i;
        if (gm >= M) continue;
#pragma unroll
        for (int j = 0; j < NR; j++) {
            int gn = n0 + tx*NR + j;
            if (gn < N) C[(long long)gm * ldc + gn] = acc[i][j];
        }
    }
}

// ============ split-bf16 conversion kernels ============
__global__ void convA_k(const float* __restrict__ proj, __nv_bfloat16* __restrict__ A2)
{
    int idx = blockIdx.x * blockDim.x + threadIdx.x;
    if (idx >= BT_ * E_) return;
    int r = idx >> 7, k = idx & 127;
    float x = proj[idx];
    __nv_bfloat16 hi = __float2bfloat16(x);
    __nv_bfloat16 lo = __float2bfloat16(x - __bfloat162float(hi));
    __nv_bfloat16* row = A2 + (size_t)r * 384;
    row[k]       = hi;
    row[128 + k] = hi;
    row[256 + k] = lo;
}

__global__ void convB_k(const float* __restrict__ Wv, __nv_bfloat16* __restrict__ B2t)
{
    __shared__ float sh[128][65];
    int n0 = blockIdx.x * 64;
    int tid = threadIdx.x;
    for (int idx = tid; idx < 128 * 64; idx += 256) {
        int k = idx >> 6, n = idx & 63;
        float v = 0.f;
        if (n0 + n < V_) v = Wv[(size_t)k * V_ + n0 + n];
        sh[k][n] = v;
    }
    __syncthreads();
    for (int idx = tid; idx < 64 * 128; idx += 256) {
        int n = idx >> 7, k = idx & 127;
        if (n0 + n >= V_) continue;
        float x = sh[k][n];
        __nv_bfloat16 hi = __float2bfloat16(x);
        __nv_bfloat16 lo = __float2bfloat16(x - __bfloat162float(hi));
        __nv_bfloat16* row = B2t + (size_t)(n0 + n) * 384;
        row[k]       = hi;
        row[128 + k] = lo;
        row[256 + k] = hi;
    }
}

// ---------------- zero rsum (per replay) ----------------
__global__ void zero_rsum_k(float* __restrict__ rsum)
{
    int i = blockIdx.x * blockDim.x + threadIdx.x;
    if (i < BT_) rsum[i] = 0.f;
}

// ============ tensor-core vocab GEMM, double-buffered, fused exp epilogue ============
// Writes exp(logit) to C and atomically accumulates per-row sum-exp into rsum.
// (logits are provably small: |x| < ~10, so exp without max-subtraction is safe.)
#define MBM 128
#define MBN 64
#define MKC 32
#define MST 40
#define NCHUNK 12

__global__ void __launch_bounds__(256) vocab_mma_k(
    const __nv_bfloat16* __restrict__ A2,   // (BT, 384) row-major
    const __nv_bfloat16* __restrict__ B2t,  // (V, 384)  row-major
    float* __restrict__ C,                  // (BT, V) -> exp(logits)
    float* __restrict__ rsum)               // (BT,)
{
    __shared__ __nv_bfloat16 As[2][MBM * MST];
    __shared__ __nv_bfloat16 Bs[2][MBN * MST];
    __shared__ float rowsum[MBM];
    int m0 = blockIdx.y * MBM;
    int n0 = blockIdx.x * MBN;
    int tid  = threadIdx.x;
    int lane = tid & 31, warp = tid >> 5;
    int wm = warp & 3, wn = warp >> 2;
    int group = lane >> 2, tig = lane & 3;

    int arow0 = tid >> 2,         ac0 = (tid & 3) << 3;
    int arow1 = (tid + 256) >> 2, ac1 = ac0;
    int brow  = tid >> 2,         bc  = (tid & 3) << 3;
    int bguard = (n0 + brow < V_);

    float acc[2][4][4];
#pragma unroll
    for (int i = 0; i < 2; i++)
#pragma unroll
        for (int j = 0; j < 4; j++)
#pragma unroll
            for (int q = 0; q < 4; q++) acc[i][j][q] = 0.f;

    for (int i = tid; i < MBM; i += 256) rowsum[i] = 0.f;

    uint4 ra0, ra1, rb;
    ra0 = *(const uint4*)(A2 + (size_t)(m0 + arow0) * 384 + ac0);
    ra1 = *(const uint4*)(A2 + (size_t)(m0 + arow1) * 384 + ac1);
    rb  = make_uint4(0u,0u,0u,0u);
    if (bguard) rb = *(const uint4*)(B2t + (size_t)(n0 + brow) * 384 + bc);
    *(uint4*)(As[0] + arow0 * MST + ac0) = ra0;
    *(uint4*)(As[0] + arow1 * MST + ac1) = ra1;
    *(uint4*)(Bs[0] + brow  * MST + bc ) = rb;
    __syncthreads();

    for (int c = 0; c < NCHUNK; c++) {
        int buf = c & 1;
        int kn = (c + 1) * MKC;
        if (c + 1 < NCHUNK) {
            ra0 = *(const uint4*)(A2 + (size_t)(m0 + arow0) * 384 + kn + ac0);
            ra1 = *(const uint4*)(A2 + (size_t)(m0 + arow1) * 384 + kn + ac1);
            if (bguard) rb = *(const uint4*)(B2t + (size_t)(n0 + brow) * 384 + kn + bc);
        }
        const __nv_bfloat16* Ab = As[buf];
        const __nv_bfloat16* Bb = Bs[buf];
#pragma unroll
        for (int ks = 0; ks < MKC; ks += 16) {
            unsigned af[2][4];
#pragma unroll
            for (int mi = 0; mi < 2; mi++) {
                int r = wm * 32 + mi * 16;
                af[mi][0] = *(const unsigned*)(Ab + (r + group    ) * MST + ks + tig*2    );
                af[mi][1] = *(const unsigned*)(Ab + (r + group + 8) * MST + ks + tig*2    );
                af[mi][2] = *(const unsigned*)(Ab + (r + group    ) * MST + ks + tig*2 + 8);
                af[mi][3] = *(const unsigned*)(Ab + (r + group + 8) * MST + ks + tig*2 + 8);
            }
            unsigned bfr[4][2];
#pragma unroll
            for (int ni = 0; ni < 4; ni++) {
                int n = wn * 32 + ni * 8 + group;
                bfr[ni][0] = *(const unsigned*)(Bb + n * MST + ks + tig*2    );
                bfr[ni][1] = *(const unsigned*)(Bb + n * MST + ks + tig*2 + 8);
            }
#pragma unroll
            for (int mi = 0; mi < 2; mi++)
#pragma unroll
                for (int ni = 0; ni < 4; ni++) {
                    float* c4 = acc[mi][ni];
                    asm volatile(
                        "mma.sync.aligned.m16n8k16.row.col.f32.bf16.bf16.f32 "
                        "{%0,%1,%2,%3}, {%4,%5,%6,%7}, {%8,%9}, {%0,%1,%2,%3};\n"
                        : "+f"(c4[0]), "+f"(c4[1]), "+f"(c4[2]), "+f"(c4[3])
                        : "r"(af[mi][0]), "r"(af[mi][1]), "r"(af[mi][2]), "r"(af[mi][3]),
                          "r"(bfr[ni][0]), "r"(bfr[ni][1]));
                }
        }
        if (c + 1 < NCHUNK) {
            int nb = 1 - buf;
            *(uint4*)(As[nb] + arow0 * MST + ac0) = ra0;
            *(uint4*)(As[nb] + arow1 * MST + ac1) = ra1;
            *(uint4*)(Bs[nb] + brow  * MST + bc ) = rb;
            __syncthreads();
        }
    }

    // epilogue: exp + store + per-row sum
#pragma unroll
    for (int mi = 0; mi < 2; mi++) {
        int rloc = wm * 32 + mi * 16 + group;
        int r = m0 + rloc;
        float psumA = 0.f, psumB = 0.f;
#pragma unroll
        for (int ni = 0; ni < 4; ni++) {
            int ccol = n0 + wn * 32 + ni * 8 + tig * 2;
            if (ccol < V_) {
                float* c4 = acc[mi][ni];
                float e0 = __expf(c4[0]), e1 = __expf(c4[1]);
                float e2 = __expf(c4[2]), e3 = __expf(c4[3]);
                *(float2*)(C + (size_t)r * V_ + ccol) = make_float2(e0, e1);
                *(float2*)(C + (size_t)(r + 8) * V_ + ccol) = make_float2(e2, e3);
                psumA += e0 + e1;
                psumB += e2 + e3;
            }
        }
        atomicAdd(&rowsum[rloc], psumA);
        atomicAdd(&rowsum[rloc + 8], psumB);
    }
    __syncthreads();
    for (int i = tid; i < MBM; i += 256) atomicAdd(&rsum[m0 + i], rowsum[i]);
}

// ---------------- intra-temporal: exp + running-denominator (float4 chains) -------
__global__ void temporal_k(float* __restrict__ e)
{
    int idx = blockIdx.x * blockDim.x + threadIdx.x;    // over B * L/4
    if (idx >= B_ * (L_/4)) return;
    int b = idx / (L_/4), l4 = idx % (L_/4);
    float* base = e + (size_t)b * T_ * L_ + l4 * 4;
    float4 acc = make_float4(0.f, 0.f, 0.f, 0.f);
    for (int t = 0; t < T_; t++) {
        float4 x = *(float4*)(base + (size_t)t * L_);
        float4 ex;
        ex.x = __expf(x.x); ex.y = __expf(x.y); ex.z = __expf(x.z); ex.w = __expf(x.w);
        float4 o;
        if (t == 0) o = ex;
        else {
            o.x = ex.x / acc.x; o.y = ex.y / acc.y;
            o.z = ex.z / acc.z; o.w = ex.w / acc.w;
        }
        *(float4*)(base + (size_t)t * L_) = o;
        acc.x += ex.x; acc.y += ex.y; acc.z += ex.z; acc.w += ex.w;
    }
}

// ---------------- normalize enc attention over L (in place) ----------------
__global__ void encnorm_k(float* __restrict__ att)
{
    int r = blockIdx.x;
    float* row = att + (size_t)r * L_;
    float acc = 0.f;
    for (int i = threadIdx.x; i < L_; i += 128) acc += row[i];
    __shared__ float sh[128];
    sh[threadIdx.x] = acc;
    __syncthreads();
    for (int st = 64; st > 0; st >>= 1) {
        if (threadIdx.x < st) sh[threadIdx.x] += sh[threadIdx.x + st];
        __syncthreads();
    }
    float inv = 1.f / sh[0];
    for (int i = threadIdx.x; i < L_; i += 128) row[i] *= inv;
}

// ---------------- fused dec self-attention: causal scores + softmax ----------------
// One block per (b,t). Replaces the 32-block batched GEMM + decsm.
__global__ void __launch_bounds__(256) dec_att_k(
    const float* __restrict__ Xd, const float* __restrict__ dec,
    float* __restrict__ datt)
{
    int r = blockIdx.x;            // b*T + t
    int b = r / T_, t = r % T_;
    int tid = threadIdx.x;
    float* orow = datt + (size_t)r * T_;
    if (t == 0) {
        if (tid < T_) orow[tid] = 0.f;
        return;
    }
    __shared__ float4 xs[H2_/4];
    __shared__ float sc[T_];
    for (int i = tid; i < H2_/4; i += 256)
        xs[i] = *(const float4*)(Xd + (size_t)r * H2_ + i*4);
    __syncthreads();
    int warp = tid >> 5, lane = tid & 31;
    for (int j = warp; j < t; j += 8) {
        const float4* drow = (const float4*)(dec + ((size_t)b * T_ + j) * H2_);
        float a = 0.f;
#pragma unroll
        for (int i = 0; i < H2_/128; i++) {
            float4 x = xs[lane + 32*i];
            float4 d = drow[lane + 32*i];
            a += x.x*d.x + x.y*d.y + x.z*d.z + x.w*d.w;
        }
#pragma unroll
        for (int o = 16; o > 0; o >>= 1) a += __shfl_xor_sync(0xffffffffu, a, o);
        if (lane == 0) sc[j] = a;
    }
    __syncthreads();
    if (warp == 0) {
        float v1 = (lane < t) ? sc[lane] : -1e30f;
        float v2 = (lane + 32 < t) ? sc[lane + 32] : -1e30f;
        float m = fmaxf(v1, v2);
#pragma unroll
        for (int o = 16; o > 0; o >>= 1) m = fmaxf(m, __shfl_xor_sync(0xffffffffu, m, o));
        float e1 = (lane < t) ? __expf(v1 - m) : 0.f;
        float e2 = (lane + 32 < t) ? __expf(v2 - m) : 0.f;
        float s = e1 + e2;
#pragma unroll
        for (int o = 16; o > 0; o >>= 1) s += __shfl_xor_sync(0xffffffffu, s, o);
        float inv = 1.f / s;
        if (lane < T_) orow[lane] = e1 * inv;
        if (lane + 32 < T_) orow[lane + 32] = e2 * inv;
    }
}

// ---------------- copy h into cat[:, 0:H2] ----------------
__global__ void copyh_k(const float* __restrict__ dec, float* __restrict__ cat)
{
    int idx = blockIdx.x * blockDim.x + threadIdx.x;
    if (idx >= BT_ * H2_) return;
    int r = idx >> 9, h = idx & 511;
    cat[(size_t)r * (3*H2_) + h] = dec[idx];
}

// ---------------- copy gate p = sigmoid(cat . w_ptr + b) ----------------
__global__ void pgate_k(const float* __restrict__ cat, const float* __restrict__ w,
                        const float* __restrict__ bb, float* __restrict__ p)
{
    int r = blockIdx.x;
    const float* row = cat + (size_t)r * (3*H2_);
    float acc = 0.f;
    for (int i = threadIdx.x; i < 3*H2_; i += 256) acc += row[i] * w[i];
    __shared__ float sh[256];
    sh[threadIdx.x] = acc;
    __syncthreads();
    for (int st = 128; st > 0; st >>= 1) {
        if (threadIdx.x < st) sh[threadIdx.x] += sh[threadIdx.x + st];
        __syncthreads();
    }
    if (threadIdx.x == 0) p[r] = 1.f / (1.f + __expf(-(sh[0] + bb[0])));
}

// ---------------- final write: (1-p)/rsum * explogits into [:, :V], zero OOV tail --
__global__ void final_k(const float* __restrict__ explogits,
                        const float* __restrict__ rsum, const float* __restrict__ p,
                        float* __restrict__ out)
{
    int r = blockIdx.y;
    int v4 = blockIdx.x * blockDim.x + threadIdx.x;
    if (v4 >= VEXT_/4) return;
    float4 o = make_float4(0.f, 0.f, 0.f, 0.f);
    if (v4 < V_/4) {
        float sc = (1.f - p[r]) / rsum[r];
        float4 x = *(const float4*)(explogits + (size_t)r * V_ + v4*4);
        o.x = sc * x.x; o.y = sc * x.y; o.z = sc * x.z; o.w = sc * x.w;
    }
    *(float4*)(out + (size_t)r * VEXT_ + v4*4) = o;
}

// ---------------- pointer scatter-add: out[r, ev[b,l]] += p[r]*enc_att[r,l] -------
__global__ void scatter_k(const int* __restrict__ ev, const float* __restrict__ att,
                          const float* __restrict__ p, float* __restrict__ out)
{
    int idx = blockIdx.x * blockDim.x + threadIdx.x;
    if (idx >= BT_ * L_) return;
    int l = idx % L_;
    int r = idx / L_;
    int b = r / T_;
    float val = p[r] * att[idx];
    atomicAdd(&out[(size_t)r * VEXT_ + ev[b * L_ + l]], val);
}

// ---------------- host orchestration ----------------
template<int TMv, int TNv>
static void gemm(int M, int N, int K,
                 const float* A, int lda, long long sA,
                 const float* B, int ldb, long long sB, int transB,
                 float* C, int ldc, long long sC, int batch)
{
    dim3 grid((N + TNv - 1) / TNv, (M + TMv - 1) / TMv, batch);
    gemm_t<TMv, TNv><<<grid, 256>>>(M, N, K, A, lda, sA, B, ldb, sB, transB, C, ldc, sC);
}

extern "C" void kernel_launch(void* const* d_in, const int* in_sizes, int n_in,
                              void* d_out, int out_size)
{
    const float* dec     = (const float*)d_in[0];   // (B,T,H2)
    const float* enc     = (const float*)d_in[1];   // (B,L,H2)
    const float* W_enc   = (const float*)d_in[2];   // (H2,H2)
    const float* W_dec   = (const float*)d_in[3];   // (H2,H2)
    const float* W_proj  = (const float*)d_in[4];   // (3H2,E)
    const float* W_vocab = (const float*)d_in[5];   // (E,V)
    const float* w_ptr   = (const float*)d_in[6];   // (3H2,)
    const float* b_ptr   = (const float*)d_in[7];   // (1,)
    const int*   ev      = (const int*)d_in[8];     // (B,L)
    float* out = (float*)d_out;                     // (B,T,VEXT)

    float *Xe, *Xd, *att, *s, *cat, *proj, *p, *rsum, *logits;
    __nv_bfloat16 *A2, *B2t;
    cudaGetSymbolAddress((void**)&Xe,     g_Xe);
    cudaGetSymbolAddress((void**)&Xd,     g_Xd);
    cudaGetSymbolAddress((void**)&att,    g_att);
    cudaGetSymbolAddress((void**)&s,      g_s);
    cudaGetSymbolAddress((void**)&cat,    g_cat);
    cudaGetSymbolAddress((void**)&proj,   g_proj);
    cudaGetSymbolAddress((void**)&p,      g_p);
    cudaGetSymbolAddress((void**)&rsum,   g_rsum);
    cudaGetSymbolAddress((void**)&logits, g_logits);
    cudaGetSymbolAddress((void**)&A2,     g_A2);
    cudaGetSymbolAddress((void**)&B2t,    g_B2t);

    // 0) split/transpose W_vocab + zero rsum (independent of everything else)
    convB_k<<<(V_ + 63) / 64, 256>>>(W_vocab, B2t);
    zero_rsum_k<<<(BT_ + 255)/256, 256>>>(rsum);

    // 1) bilinear projections of decoder hiddens
    gemm<32,64>(BT_, H2_, H2_, dec, H2_, 0, W_enc, H2_, 0, 0, Xe, H2_, 0, 1);
    gemm<32,64>(BT_, H2_, H2_, dec, H2_, 0, W_dec, H2_, 0, 0, Xd, H2_, 0, 1);

    // 2) encoder attention scores e[b,t,l] = Xe[b,t,:] . enc[b,l,:]   (batched, B^T)
    gemm<32,64>(T_, L_, H2_, Xe, H2_, (long long)T_*H2_,
                enc, H2_, (long long)L_*H2_, 1,
                att, L_, (long long)T_*L_, B_);

    // 3) intra-temporal exp + cumulative denominator, then normalize over L
    temporal_k<<<(B_*(L_/4) + 255)/256, 256>>>(att);
    encnorm_k<<<BT_, 128>>>(att);

    // 4) fused decoder self-attention (causal scores + softmax)
    dec_att_k<<<BT_, 256>>>(Xd, dec, s);

    // 5) assemble cat = [h | enc_ctx | dec_ctx]
    copyh_k<<<(BT_*H2_ + 255)/256, 256>>>(dec, cat);
    gemm<32,64>(T_, H2_, L_, att, L_, (long long)T_*L_,
                enc, H2_, (long long)L_*H2_, 0,
                cat + H2_, 3*H2_, (long long)T_*3*H2_, B_);
    gemm<32,64>(T_, H2_, T_, s, T_, (long long)T_*T_,
                dec, H2_, (long long)T_*H2_, 0,
                cat + 2*H2_, 3*H2_, (long long)T_*3*H2_, B_);

    // 6) copy gate + embedding projection
    pgate_k<<<BT_, 256>>>(cat, w_ptr, b_ptr, p);
    gemm<32,32>(BT_, E_, 3*H2_, cat, 3*H2_, 0, W_proj, E_, 0, 0, proj, E_, 0, 1);

    // 7) vocab logits via tensor cores (fused exp + row-sum epilogue)
    convA_k<<<(BT_*E_ + 255)/256, 256>>>(proj, A2);
    {
        dim3 grid((V_ + MBN - 1) / MBN, BT_ / MBM);
        vocab_mma_k<<<grid, 256>>>(A2, B2t, logits, rsum);
    }

    // 8) final distribution write + pointer scatter
    final_k<<<dim3((VEXT_/4 + 255)/256, BT_), 256>>>(logits, rsum, p, out);
    scatter_k<<<(BT_*L_ + 255)/256, 256>>>(ev, att, p, out);
}

// round 10
// speedup vs baseline: 1.2838x; 1.2838x over previous
#include <cuda_runtime.h>
#include <cuda_bf16.h>
#include <math.h>

#define B_   32
#define T_   48
#define L_   400
#define H2_  512
#define E_   128
#define V_   50000
#define OOV_ 100
#define VEXT_ 50100
#define BT_  (B_*T_)

// ---------------- scratch (static device allocations; no cudaMalloc) ----------------
__device__ float g_Xe[BT_*H2_];
__device__ float g_Xd[BT_*H2_];
__device__ float g_att[BT_*L_];        // e -> temporal -> enc_att (in place)
__device__ float g_s[BT_*T_];          // normalized dec attention
__device__ float g_cat[BT_*3*H2_];     // [h | enc_ctx | dec_ctx]
__device__ float g_proj[BT_*E_];
__device__ float g_p[BT_];
__device__ float g_rsum[BT_];
__device__ float g_logits[(size_t)BT_*V_];            // holds exp(logits), 307 MB
__device__ __nv_bfloat16 g_A2[(size_t)BT_*3*E_];      // split A: [hi|hi|lo], (BT,384)
__device__ __nv_bfloat16 g_B2t[(size_t)V_*3*E_];      // split B^T: rows [hi;lo;hi], (V,384)

// ---------------- generic tiled fp32 GEMM with register prefetch (proven) ----------
#define TM 64
#define TN 64
#define TKK 16

__global__ void gemm_k(int M, int N, int K,
                       const float* __restrict__ A, int lda, long long sA,
                       const float* __restrict__ B, int ldb, long long sB, int transB,
                       float* __restrict__ C, int ldc, long long sC)
{
    __shared__ float As[TKK][TM];
    __shared__ float Bs[TKK][TN];
    int bz = blockIdx.z;
    A += (long long)bz * sA;
    B += (long long)bz * sB;
    C += (long long)bz * sC;
    int m0 = blockIdx.y * TM;
    int n0 = blockIdx.x * TN;
    int tid = threadIdx.x;          // 0..255
    int tx = tid & 15, ty = tid >> 4;
    float acc[4][4] = {};
    float ar[4], br[4];

    // prologue: load chunk 0 into registers
#pragma unroll
    for (int i = 0; i < 4; i++) {
        int li = tid + 256 * i;
        int m = li & 63, k = li >> 6;
        int gm = m0 + m, gk = k;
        ar[i] = (gm < M && gk < K) ? A[(long long)gm * lda + gk] : 0.f;
    }
#pragma unroll
    for (int i = 0; i < 4; i++) {
        int li = tid + 256 * i;
        int n = li & 63, k = li >> 6;
        int gn = n0 + n, gk = k;
        float v = 0.f;
        if (gn < N && gk < K)
            v = transB ? B[(long long)gn * ldb + gk] : B[(long long)gk * ldb + gn];
        br[i] = v;
    }

    for (int kk = 0; kk < K; kk += TKK) {
        // commit current chunk to shared
#pragma unroll
        for (int i = 0; i < 4; i++) { int li = tid + 256*i; As[li>>6][li&63] = ar[i]; }
#pragma unroll
        for (int i = 0; i < 4; i++) { int li = tid + 256*i; Bs[li>>6][li&63] = br[i]; }
        __syncthreads();

        // prefetch next chunk (LDG latency overlapped with compute below)
        int kn = kk + TKK;
        if (kn < K) {
#pragma unroll
            for (int i = 0; i < 4; i++) {
                int li = tid + 256 * i;
                int m = li & 63, k = li >> 6;
                int gm = m0 + m, gk = kn + k;
                ar[i] = (gm < M && gk < K) ? A[(long long)gm * lda + gk] : 0.f;
            }
#pragma unroll
            for (int i = 0; i < 4; i++) {
                int li = tid + 256 * i;
                int n = li & 63, k = li >> 6;
                int gn = n0 + n, gk = kn + k;
                float v = 0.f;
                if (gn < N && gk < K)
                    v = transB ? B[(long long)gn * ldb + gk] : B[(long long)gk * ldb + gn];
                br[i] = v;
            }
        }

#pragma unroll
        for (int k = 0; k < TKK; k++) {
            float a0[4], b0[4];
#pragma unroll
            for (int i = 0; i < 4; i++) a0[i] = As[k][ty*4 + i];
#pragma unroll
            for (int j = 0; j < 4; j++) b0[j] = Bs[k][tx*4 + j];
#pragma unroll
            for (int i = 0; i < 4; i++)
#pragma unroll
                for (int j = 0; j < 4; j++)
                    acc[i][j] = fmaf(a0[i], b0[j], acc[i][j]);
        }
        __syncthreads();
    }
#pragma unroll
    for (int i = 0; i < 4; i++) {
        int gm = m0 + ty*4 + i;
        if (gm >= M) continue;
#pragma unroll
        for (int j = 0; j < 4; j++) {
            int gn = n0 + tx*4 + j;
            if (gn < N) C[(long long)gm * ldc + gn] = acc[i][j];
        }
    }
}

// ============ split-bf16 conversion kernels ============
__global__ void convA_k(const float* __restrict__ proj, __nv_bfloat16* __restrict__ A2)
{
    int idx = blockIdx.x * blockDim.x + threadIdx.x;
    if (idx >= BT_ * E_) return;
    int r = idx >> 7, k = idx & 127;
    float x = proj[idx];
    __nv_bfloat16 hi = __float2bfloat16(x);
    __nv_bfloat16 lo = __float2bfloat16(x - __bfloat162float(hi));
    __nv_bfloat16* row = A2 + (size_t)r * 384;
    row[k]       = hi;
    row[128 + k] = hi;
    row[256 + k] = lo;
}

__global__ void convB_k(const float* __restrict__ Wv, __nv_bfloat16* __restrict__ B2t)
{
    __shared__ float sh[128][65];
    int n0 = blockIdx.x * 64;
    int tid = threadIdx.x;
    for (int idx = tid; idx < 128 * 64; idx += 256) {
        int k = idx >> 6, n = idx & 63;
        float v = 0.f;
        if (n0 + n < V_) v = Wv[(size_t)k * V_ + n0 + n];
        sh[k][n] = v;
    }
    __syncthreads();
    for (int idx = tid; idx < 64 * 128; idx += 256) {
        int n = idx >> 7, k = idx & 127;
        if (n0 + n >= V_) continue;
        float x = sh[k][n];
        __nv_bfloat16 hi = __float2bfloat16(x);
        __nv_bfloat16 lo = __float2bfloat16(x - __bfloat162float(hi));
        __nv_bfloat16* row = B2t + (size_t)(n0 + n) * 384;
        row[k]       = hi;
        row[128 + k] = lo;
        row[256 + k] = hi;
    }
}

// ---------------- zero rsum (per replay) ----------------
__global__ void zero_rsum_k(float* __restrict__ rsum)
{
    int i = blockIdx.x * blockDim.x + threadIdx.x;
    if (i < BT_) rsum[i] = 0.f;
}

// ============ tensor-core vocab GEMM, double-buffered, fused exp epilogue ============
#define MBM 128
#define MBN 64
#define MKC 32
#define MST 40
#define NCHUNK 12

__global__ void __launch_bounds__(256) vocab_mma_k(
    const __nv_bfloat16* __restrict__ A2,   // (BT, 384) row-major
    const __nv_bfloat16* __restrict__ B2t,  // (V, 384)  row-major
    float* __restrict__ C,                  // (BT, V) -> exp(logits)
    float* __restrict__ rsum)               // (BT,)
{
    __shared__ __nv_bfloat16 As[2][MBM * MST];
    __shared__ __nv_bfloat16 Bs[2][MBN * MST];
    __shared__ float rowsum[MBM];
    int m0 = blockIdx.y * MBM;
    int n0 = blockIdx.x * MBN;
    int tid  = threadIdx.x;
    int lane = tid & 31, warp = tid >> 5;
    int wm = warp & 3, wn = warp >> 2;
    int group = lane >> 2, tig = lane & 3;

    int arow0 = tid >> 2,         ac0 = (tid & 3) << 3;
    int arow1 = (tid + 256) >> 2, ac1 = ac0;
    int brow  = tid >> 2,         bc  = (tid & 3) << 3;
    int bguard = (n0 + brow < V_);

    float acc[2][4][4];
#pragma unroll
    for (int i = 0; i < 2; i++)
#pragma unroll
        for (int j = 0; j < 4; j++)
#pragma unroll
            for (int q = 0; q < 4; q++) acc[i][j][q] = 0.f;

    for (int i = tid; i < MBM; i += 256) rowsum[i] = 0.f;

    uint4 ra0, ra1, rb;
    ra0 = *(const uint4*)(A2 + (size_t)(m0 + arow0) * 384 + ac0);
    ra1 = *(const uint4*)(A2 + (size_t)(m0 + arow1) * 384 + ac1);
    rb  = make_uint4(0u,0u,0u,0u);
    if (bguard) rb = *(const uint4*)(B2t + (size_t)(n0 + brow) * 384 + bc);
    *(uint4*)(As[0] + arow0 * MST + ac0) = ra0;
    *(uint4*)(As[0] + arow1 * MST + ac1) = ra1;
    *(uint4*)(Bs[0] + brow  * MST + bc ) = rb;
    __syncthreads();

    for (int c = 0; c < NCHUNK; c++) {
        int buf = c & 1;
        int kn = (c + 1) * MKC;
        if (c + 1 < NCHUNK) {
            ra0 = *(const uint4*)(A2 + (size_t)(m0 + arow0) * 384 + kn + ac0);
            ra1 = *(const uint4*)(A2 + (size_t)(m0 + arow1) * 384 + kn + ac1);
            if (bguard) rb = *(const uint4*)(B2t + (size_t)(n0 + brow) * 384 + kn + bc);
        }
        const __nv_bfloat16* Ab = As[buf];
        const __nv_bfloat16* Bb = Bs[buf];
#pragma unroll
        for (int ks = 0; ks < MKC; ks += 16) {
            unsigned af[2][4];
#pragma unroll
            for (int mi = 0; mi < 2; mi++) {
                int r = wm * 32 + mi * 16;
                af[mi][0] = *(const unsigned*)(Ab + (r + group    ) * MST + ks + tig*2    );
                af[mi][1] = *(const unsigned*)(Ab + (r + group + 8) * MST + ks + tig*2    );
                af[mi][2] = *(const unsigned*)(Ab + (r + group    ) * MST + ks + tig*2 + 8);
                af[mi][3] = *(const unsigned*)(Ab + (r + group + 8) * MST + ks + tig*2 + 8);
            }
            unsigned bfr[4][2];
#pragma unroll
            for (int ni = 0; ni < 4; ni++) {
                int n = wn * 32 + ni * 8 + group;
                bfr[ni][0] = *(const unsigned*)(Bb + n * MST + ks + tig*2    );
                bfr[ni][1] = *(const unsigned*)(Bb + n * MST + ks + tig*2 + 8);
            }
#pragma unroll
            for (int mi = 0; mi < 2; mi++)
#pragma unroll
                for (int ni = 0; ni < 4; ni++) {
                    float* c4 = acc[mi][ni];
                    asm volatile(
                        "mma.sync.aligned.m16n8k16.row.col.f32.bf16.bf16.f32 "
                        "{%0,%1,%2,%3}, {%4,%5,%6,%7}, {%8,%9}, {%0,%1,%2,%3};\n"
                        : "+f"(c4[0]), "+f"(c4[1]), "+f"(c4[2]), "+f"(c4[3])
                        : "r"(af[mi][0]), "r"(af[mi][1]), "r"(af[mi][2]), "r"(af[mi][3]),
                          "r"(bfr[ni][0]), "r"(bfr[ni][1]));
                }
        }
        if (c + 1 < NCHUNK) {
            int nb = 1 - buf;
            *(uint4*)(As[nb] + arow0 * MST + ac0) = ra0;
            *(uint4*)(As[nb] + arow1 * MST + ac1) = ra1;
            *(uint4*)(Bs[nb] + brow  * MST + bc ) = rb;
            __syncthreads();
        }
    }

    // epilogue: exp + store + per-row sum (logits provably small; no max needed)
#pragma unroll
    for (int mi = 0; mi < 2; mi++) {
        int rloc = wm * 32 + mi * 16 + group;
        int r = m0 + rloc;
        float psumA = 0.f, psumB = 0.f;
#pragma unroll
        for (int ni = 0; ni < 4; ni++) {
            int ccol = n0 + wn * 32 + ni * 8 + tig * 2;
            if (ccol < V_) {
                float* c4 = acc[mi][ni];
                float e0 = __expf(c4[0]), e1 = __expf(c4[1]);
                float e2 = __expf(c4[2]), e3 = __expf(c4[3]);
                *(float2*)(C + (size_t)r * V_ + ccol) = make_float2(e0, e1);
                *(float2*)(C + (size_t)(r + 8) * V_ + ccol) = make_float2(e2, e3);
                psumA += e0 + e1;
                psumB += e2 + e3;
            }
        }
        atomicAdd(&rowsum[rloc], psumA);
        atomicAdd(&rowsum[rloc + 8], psumB);
    }
    __syncthreads();
    for (int i = tid; i < MBM; i += 256) atomicAdd(&rsum[m0 + i], rowsum[i]);
}

// ---------------- intra-temporal: exp + running-denominator (float4 chains) -------
__global__ void temporal_k(float* __restrict__ e)
{
    int idx = blockIdx.x * blockDim.x + threadIdx.x;    // over B * L/4
    if (idx >= B_ * (L_/4)) return;
    int b = idx / (L_/4), l4 = idx % (L_/4);
    float* base = e + (size_t)b * T_ * L_ + l4 * 4;
    float4 acc = make_float4(0.f, 0.f, 0.f, 0.f);
    for (int t = 0; t < T_; t++) {
        float4 x = *(float4*)(base + (size_t)t * L_);
        float4 ex;
        ex.x = __expf(x.x); ex.y = __expf(x.y); ex.z = __expf(x.z); ex.w = __expf(x.w);
        float4 o;
        if (t == 0) o = ex;
        else {
            o.x = ex.x / acc.x; o.y = ex.y / acc.y;
            o.z = ex.z / acc.z; o.w = ex.w / acc.w;
        }
        *(float4*)(base + (size_t)t * L_) = o;
        acc.x += ex.x; acc.y += ex.y; acc.z += ex.z; acc.w += ex.w;
    }
}

// ---------------- normalize enc attention over L (in place) ----------------
__global__ void encnorm_k(float* __restrict__ att)
{
    int r = blockIdx.x;
    float* row = att + (size_t)r * L_;
    float acc = 0.f;
    for (int i = threadIdx.x; i < L_; i += 128) acc += row[i];
    __shared__ float sh[128];
    sh[threadIdx.x] = acc;
    __syncthreads();
    for (int st = 64; st > 0; st >>= 1) {
        if (threadIdx.x < st) sh[threadIdx.x] += sh[threadIdx.x + st];
        __syncthreads();
    }
    float inv = 1.f / sh[0];
    for (int i = threadIdx.x; i < L_; i += 128) row[i] *= inv;
}

// ---------------- fused dec self-attention: causal scores + softmax ----------------
__global__ void __launch_bounds__(256) dec_att_k(
    const float* __restrict__ Xd, const float* __restrict__ dec,
    float* __restrict__ datt)
{
    int r = blockIdx.x;            // b*T + t
    int b = r / T_, t = r % T_;
    int tid = threadIdx.x;
    float* orow = datt + (size_t)r * T_;
    if (t == 0) {
        if (tid < T_) orow[tid] = 0.f;
        return;
    }
    __shared__ float4 xs[H2_/4];
    __shared__ float sc[T_];
    for (int i = tid; i < H2_/4; i += 256)
        xs[i] = *(const float4*)(Xd + (size_t)r * H2_ + i*4);
    __syncthreads();
    int warp = tid >> 5, lane = tid & 31;
    for (int j = warp; j < t; j += 8) {
        const float4* drow = (const float4*)(dec + ((size_t)b * T_ + j) * H2_);
        float a = 0.f;
#pragma unroll
        for (int i = 0; i < H2_/128; i++) {
            float4 x = xs[lane + 32*i];
            float4 d = drow[lane + 32*i];
            a += x.x*d.x + x.y*d.y + x.z*d.z + x.w*d.w;
        }
#pragma unroll
        for (int o = 16; o > 0; o >>= 1) a += __shfl_xor_sync(0xffffffffu, a, o);
        if (lane == 0) sc[j] = a;
    }
    __syncthreads();
    if (warp == 0) {
        float v1 = (lane < t) ? sc[lane] : -1e30f;
        float v2 = (lane + 32 < t) ? sc[lane + 32] : -1e30f;
        float m = fmaxf(v1, v2);
#pragma unroll
        for (int o = 16; o > 0; o >>= 1) m = fmaxf(m, __shfl_xor_sync(0xffffffffu, m, o));
        float e1 = (lane < t) ? __expf(v1 - m) : 0.f;
        float e2 = (lane + 32 < t) ? __expf(v2 - m) : 0.f;
        float s = e1 + e2;
#pragma unroll
        for (int o = 16; o > 0; o >>= 1) s += __shfl_xor_sync(0xffffffffu, s, o);
        float inv = 1.f / s;
        if (lane < T_) orow[lane] = e1 * inv;
        if (lane + 32 < T_) orow[lane + 32] = e2 * inv;
    }
}

// ---------------- copy h into cat[:, 0:H2] ----------------
__global__ void copyh_k(const float* __restrict__ dec, float* __restrict__ cat)
{
    int idx = blockIdx.x * blockDim.x + threadIdx.x;
    if (idx >= BT_ * H2_) return;
    int r = idx >> 9, h = idx & 511;
    cat[(size_t)r * (3*H2_) + h] = dec[idx];
}

// ---------------- copy gate p = sigmoid(cat . w_ptr + b) ----------------
__global__ void pgate_k(const float* __restrict__ cat, const float* __restrict__ w,
                        const float* __restrict__ bb, float* __restrict__ p)
{
    int r = blockIdx.x;
    const float* row = cat + (size_t)r * (3*H2_);
    float acc = 0.f;
    for (int i = threadIdx.x; i < 3*H2_; i += 256) acc += row[i] * w[i];
    __shared__ float sh[256];
    sh[threadIdx.x] = acc;
    __syncthreads();
    for (int st = 128; st > 0; st >>= 1) {
        if (threadIdx.x < st) sh[threadIdx.x] += sh[threadIdx.x + st];
        __syncthreads();
    }
    if (threadIdx.x == 0) p[r] = 1.f / (1.f + __expf(-(sh[0] + bb[0])));
}

// ---------------- final write: (1-p)/rsum * explogits into [:, :V], zero OOV tail --
__global__ void final_k(const float* __restrict__ explogits,
                        const float* __restrict__ rsum, const float* __restrict__ p,
                        float* __restrict__ out)
{
    int r = blockIdx.y;
    int v4 = blockIdx.x * blockDim.x + threadIdx.x;
    if (v4 >= VEXT_/4) return;
    float4 o = make_float4(0.f, 0.f, 0.f, 0.f);
    if (v4 < V_/4) {
        float sc = (1.f - p[r]) / rsum[r];
        float4 x = *(const float4*)(explogits + (size_t)r * V_ + v4*4);
        o.x = sc * x.x; o.y = sc * x.y; o.z = sc * x.z; o.w = sc * x.w;
    }
    *(float4*)(out + (size_t)r * VEXT_ + v4*4) = o;
}

// ---------------- pointer scatter-add: out[r, ev[b,l]] += p[r]*enc_att[r,l] -------
__global__ void scatter_k(const int* __restrict__ ev, const float* __restrict__ att,
                          const float* __restrict__ p, float* __restrict__ out)
{
    int idx = blockIdx.x * blockDim.x + threadIdx.x;
    if (idx >= BT_ * L_) return;
    int l = idx % L_;
    int r = idx / L_;
    int b = r / T_;
    float val = p[r] * att[idx];
    atomicAdd(&out[(size_t)r * VEXT_ + ev[b * L_ + l]], val);
}

// ---------------- host orchestration ----------------
static void gemm(int M, int N, int K,
                 const float* A, int lda, long long sA,
                 const float* B, int ldb, long long sB, int transB,
                 float* C, int ldc, long long sC, int batch)
{
    dim3 grid((N + TN - 1) / TN, (M + TM - 1) / TM, batch);
    gemm_k<<<grid, 256>>>(M, N, K, A, lda, sA, B, ldb, sB, transB, C, ldc, sC);
}

extern "C" void kernel_launch(void* const* d_in, const int* in_sizes, int n_in,
                              void* d_out, int out_size)
{
    const float* dec     = (const float*)d_in[0];   // (B,T,H2)
    const float* enc     = (const float*)d_in[1];   // (B,L,H2)
    const float* W_enc   = (const float*)d_in[2];   // (H2,H2)
    const float* W_dec   = (const float*)d_in[3];   // (H2,H2)
    const float* W_proj  = (const float*)d_in[4];   // (3H2,E)
    const float* W_vocab = (const float*)d_in[5];   // (E,V)
    const float* w_ptr   = (const float*)d_in[6];   // (3H2,)
    const float* b_ptr   = (const float*)d_in[7];   // (1,)
    const int*   ev      = (const int*)d_in[8];     // (B,L)
    float* out = (float*)d_out;                     // (B,T,VEXT)

    float *Xe, *Xd, *att, *s, *cat, *proj, *p, *rsum, *logits;
    __nv_bfloat16 *A2, *B2t;
    cudaGetSymbolAddress((void**)&Xe,     g_Xe);
    cudaGetSymbolAddress((void**)&Xd,     g_Xd);
    cudaGetSymbolAddress((void**)&att,    g_att);
    cudaGetSymbolAddress((void**)&s,      g_s);
    cudaGetSymbolAddress((void**)&cat,    g_cat);
    cudaGetSymbolAddress((void**)&proj,   g_proj);
    cudaGetSymbolAddress((void**)&p,      g_p);
    cudaGetSymbolAddress((void**)&rsum,   g_rsum);
    cudaGetSymbolAddress((void**)&logits, g_logits);
    cudaGetSymbolAddress((void**)&A2,     g_A2);
    cudaGetSymbolAddress((void**)&B2t,    g_B2t);

    // 0) split/transpose W_vocab + zero rsum (independent of everything else)
    convB_k<<<(V_ + 63) / 64, 256>>>(W_vocab, B2t);
    zero_rsum_k<<<(BT_ + 255)/256, 256>>>(rsum);

    // 1) bilinear projections of decoder hiddens
    gemm(BT_, H2_, H2_, dec, H2_, 0, W_enc, H2_, 0, 0, Xe, H2_, 0, 1);
    gemm(BT_, H2_, H2_, dec, H2_, 0, W_dec, H2_, 0, 0, Xd, H2_, 0, 1);

    // 2) encoder attention scores e[b,t,l] = Xe[b,t,:] . enc[b,l,:]   (batched, B^T)
    gemm(T_, L_, H2_, Xe, H2_, (long long)T_*H2_,
         enc, H2_, (long long)L_*H2_, 1,
         att, L_, (long long)T_*L_, B_);

    // 3) intra-temporal exp + cumulative denominator, then normalize over L
    temporal_k<<<(B_*(L_/4) + 255)/256, 256>>>(att);
    encnorm_k<<<BT_, 128>>>(att);

    // 4) fused decoder self-attention (causal scores + softmax)
    dec_att_k<<<BT_, 256>>>(Xd, dec, s);

    // 5) assemble cat = [h | enc_ctx | dec_ctx]
    copyh_k<<<(BT_*H2_ + 255)/256, 256>>>(dec, cat);
    gemm(T_, H2_, L_, att, L_, (long long)T_*L_,
         enc, H2_, (long long)L_*H2_, 0,
         cat + H2_, 3*H2_, (long long)T_*3*H2_, B_);
    gemm(T_, H2_, T_, s, T_, (long long)T_*T_,
         dec, H2_, (long long)T_*H2_, 0,
         cat + 2*H2_, 3*H2_, (long long)T_*3*H2_, B_);

    // 6) copy gate + embedding projection
    pgate_k<<<BT_, 256>>>(cat, w_ptr, b_ptr, p);
    gemm(BT_, E_, 3*H2_, cat, 3*H2_, 0, W_proj, E_, 0, 0, proj, E_, 0, 1);

    // 7) vocab logits via tensor cores (fused exp + row-sum epilogue)
    convA_k<<<(BT_*E_ + 255)/256, 256>>>(proj, A2);
    {
        dim3 grid((V_ + MBN - 1) / MBN, BT_ / MBM);
        vocab_mma_k<<<grid, 256>>>(A2, B2t, logits, rsum);
    }

    // 8) final distribution write + pointer scatter
    final_k<<<dim3((VEXT_/4 + 255)/256, BT_), 256>>>(logits, rsum, p, out);
    scatter_k<<<(BT_*L_ + 255)/256, 256>>>(ev, att, p, out);
}

// round 14
// speedup vs baseline: 1.4389x; 1.1209x over previous
#include <cuda_runtime.h>
#include <cuda_bf16.h>
#include <math.h>

#define B_   32
#define T_   48
#define L_   400
#define H2_  512
#define E_   128
#define V_   50000
#define OOV_ 100
#define VEXT_ 50100
#define BT_  (B_*T_)

// ---------------- scratch (static device allocations; no cudaMalloc) ----------------
__device__ float g_Xe[BT_*H2_];
__device__ float g_Xd[BT_*H2_];
__device__ float g_att[BT_*L_];
__device__ float g_s[BT_*T_];
__device__ float g_cat[BT_*3*H2_];
__device__ float g_proj[BT_*E_];
__device__ float g_p[BT_];
__device__ float g_rsum[BT_];
__device__ float g_logits[(size_t)BT_*V_];            // exp(logits), 307 MB
__device__ __nv_bfloat16 g_A2[(size_t)BT_*3*E_];      // vocab A split (BT,384)
__device__ __nv_bfloat16 g_B2t[(size_t)V_*3*E_];      // vocab B^T split (V,384)
// generic split-bf16 buffers
__device__ __nv_bfloat16 g_dec2 [(size_t)BT_*3*H2_];      // (1536,1536)  A-mode
__device__ __nv_bfloat16 g_Xe2  [(size_t)BT_*3*H2_];      // (1536,1536)  A-mode
__device__ __nv_bfloat16 g_enc2 [(size_t)B_*L_*3*H2_];    // (12800,1536) B-mode
__device__ __nv_bfloat16 g_cat2 [(size_t)BT_*9*H2_];      // (1536,4608)  A-mode
__device__ __nv_bfloat16 g_Wenc2t[(size_t)H2_*3*H2_];     // (512,1536)   B-mode
__device__ __nv_bfloat16 g_Wdec2t[(size_t)H2_*3*H2_];     // (512,1536)   B-mode
__device__ __nv_bfloat16 g_Wproj2t[(size_t)E_*9*H2_];     // (128,4608)   B-mode

// ---------------- generic tiled fp32 GEMM with register prefetch (proven) ----------
#define TM 64
#define TN 64
#define TKK 16

__global__ void gemm_k(int M, int N, int K,
                       const float* __restrict__ A, int lda, long long sA,
                       const float* __restrict__ B, int ldb, long long sB, int transB,
                       float* __restrict__ C, int ldc, long long sC)
{
    __shared__ float As[TKK][TM];
    __shared__ float Bs[TKK][TN];
    int bz = blockIdx.z;
    A += (long long)bz * sA;
    B += (long long)bz * sB;
    C += (long long)bz * sC;
    int m0 = blockIdx.y * TM;
    int n0 = blockIdx.x * TN;
    int tid = threadIdx.x;
    int tx = tid & 15, ty = tid >> 4;
    float acc[4][4] = {};
    float ar[4], br[4];

#pragma unroll
    for (int i = 0; i < 4; i++) {
        int li = tid + 256 * i;
        int m = li & 63, k = li >> 6;
        int gm = m0 + m, gk = k;
        ar[i] = (gm < M && gk < K) ? A[(long long)gm * lda + gk] : 0.f;
    }
#pragma unroll
    for (int i = 0; i < 4; i++) {
        int li = tid + 256 * i;
        int n = li & 63, k = li >> 6;
        int gn = n0 + n, gk = k;
        float v = 0.f;
        if (gn < N && gk < K)
            v = transB ? B[(long long)gn * ldb + gk] : B[(long long)gk * ldb + gn];
        br[i] = v;
    }

    for (int kk = 0; kk < K; kk += TKK) {
#pragma unroll
        for (int i = 0; i < 4; i++) { int li = tid + 256*i; As[li>>6][li&63] = ar[i]; }
#pragma unroll
        for (int i = 0; i < 4; i++) { int li = tid + 256*i; Bs[li>>6][li&63] = br[i]; }
        __syncthreads();

        int kn = kk + TKK;
        if (kn < K) {
#pragma unroll
            for (int i = 0; i < 4; i++) {
                int li = tid + 256 * i;
                int m = li & 63, k = li >> 6;
                int gm = m0 + m, gk = kn + k;
                ar[i] = (gm < M && gk < K) ? A[(long long)gm * lda + gk] : 0.f;
            }
#pragma unroll
            for (int i = 0; i < 4; i++) {
                int li = tid + 256 * i;
                int n = li & 63, k = li >> 6;
                int gn = n0 + n, gk = kn + k;
                float v = 0.f;
                if (gn < N && gk < K)
                    v = transB ? B[(long long)gn * ldb + gk] : B[(long long)gk * ldb + gn];
                br[i] = v;
            }
        }

#pragma unroll
        for (int k = 0; k < TKK; k++) {
            float a0[4], b0[4];
#pragma unroll
            for (int i = 0; i < 4; i++) a0[i] = As[k][ty*4 + i];
#pragma unroll
            for (int j = 0; j < 4; j++) b0[j] = Bs[k][tx*4 + j];
#pragma unroll
            for (int i = 0; i < 4; i++)
#pragma unroll
                for (int j = 0; j < 4; j++)
                    acc[i][j] = fmaf(a0[i], b0[j], acc[i][j]);
        }
        __syncthreads();
    }
#pragma unroll
    for (int i = 0; i < 4; i++) {
        int gm = m0 + ty*4 + i;
        if (gm >= M) continue;
#pragma unroll
        for (int j = 0; j < 4; j++) {
            int gn = n0 + tx*4 + j;
            if (gn < N) C[(long long)gm * ldc + gn] = acc[i][j];
        }
    }
}

// ============ split-bf16 conversion kernels ============
// A-mode row layout: [hi | hi | lo]; B-mode: [hi | lo | hi].
__global__ void split_k(const float* __restrict__ src, __nv_bfloat16* __restrict__ dst,
                        int R, int K, int bmode)
{
    int idx = blockIdx.x * blockDim.x + threadIdx.x;
    if (idx >= R * K) return;
    int r = idx / K, k = idx - r * K;
    float x = src[idx];
    __nv_bfloat16 hi = __float2bfloat16(x);
    __nv_bfloat16 lo = __float2bfloat16(x - __bfloat162float(hi));
    __nv_bfloat16* row = dst + (size_t)r * 3 * K;
    row[k] = hi;
    if (bmode) { row[K + k] = lo; row[2*K + k] = hi; }
    else       { row[K + k] = hi; row[2*K + k] = lo; }
}

// transpose + split: src (K,N) row-major -> dst (N,3K) in B-mode layout.
__global__ void transsplit_k(const float* __restrict__ src, __nv_bfloat16* __restrict__ dst,
                             int K, int N)
{
    __shared__ float sh[64][65];
    int n0 = blockIdx.x * 64;
    int k0 = blockIdx.y * 64;
    int tid = threadIdx.x;
    for (int idx = tid; idx < 64*64; idx += 256) {
        int kk = idx >> 6, nn = idx & 63;
        float v = 0.f;
        if (k0 + kk < K && n0 + nn < N) v = src[(size_t)(k0 + kk) * N + n0 + nn];
        sh[kk][nn] = v;
    }
    __syncthreads();
    for (int idx = tid; idx < 64*64; idx += 256) {
        int nn = idx >> 6, kk = idx & 63;
        if (n0 + nn >= N || k0 + kk >= K) continue;
        float x = sh[kk][nn];
        __nv_bfloat16 hi = __float2bfloat16(x);
        __nv_bfloat16 lo = __float2bfloat16(x - __bfloat162float(hi));
        __nv_bfloat16* row = dst + (size_t)(n0 + nn) * 3 * K;
        row[k0 + kk]         = hi;
        row[K + k0 + kk]     = lo;
        row[2*K + k0 + kk]   = hi;
    }
}

// vocab-specific converters (proven, unchanged)
__global__ void convA_k(const float* __restrict__ proj, __nv_bfloat16* __restrict__ A2)
{
    int idx = blockIdx.x * blockDim.x + threadIdx.x;
    if (idx >= BT_ * E_) return;
    int r = idx >> 7, k = idx & 127;
    float x = proj[idx];
    __nv_bfloat16 hi = __float2bfloat16(x);
    __nv_bfloat16 lo = __float2bfloat16(x - __bfloat162float(hi));
    __nv_bfloat16* row = A2 + (size_t)r * 384;
    row[k]       = hi;
    row[128 + k] = hi;
    row[256 + k] = lo;
}

__global__ void convB_k(const float* __restrict__ Wv, __nv_bfloat16* __restrict__ B2t)
{
    __shared__ float sh[128][65];
    int n0 = blockIdx.x * 64;
    int tid = threadIdx.x;
    for (int idx = tid; idx < 128 * 64; idx += 256) {
        int k = idx >> 6, n = idx & 63;
        float v = 0.f;
        if (n0 + n < V_) v = Wv[(size_t)k * V_ + n0 + n];
        sh[k][n] = v;
    }
    __syncthreads();
    for (int idx = tid; idx < 64 * 128; idx += 256) {
        int n = idx >> 7, k = idx & 127;
        if (n0 + n >= V_) continue;
        float x = sh[k][n];
        __nv_bfloat16 hi = __float2bfloat16(x);
        __nv_bfloat16 lo = __float2bfloat16(x - __bfloat162float(hi));
        __nv_bfloat16* row = B2t + (size_t)(n0 + n) * 384;
        row[k]       = hi;
        row[128 + k] = lo;
        row[256 + k] = hi;
    }
}

__global__ void zero_rsum_k(float* __restrict__ rsum)
{
    int i = blockIdx.x * blockDim.x + threadIdx.x;
    if (i < BT_) rsum[i] = 0.f;
}

// ============ generic batched split-bf16 MMA GEMM ============
// C[M,N] = A2[M,Ks] @ B2t[N,Ks]^T  (Ks = 3*K, multiple of 32), f32 output.
// 64x64 block tile, 8 warps 2(m)x4(n), warp tile 32x16, K-chunk 32, double-buffered.
#define GST 40

__global__ void __launch_bounds__(256) gmma_k(
    int M, int N, int NC,                    // NC = Ks/32
    const __nv_bfloat16* __restrict__ A2, long long sA,
    const __nv_bfloat16* __restrict__ B2, long long sB,
    float* __restrict__ C, int ldc, long long sC)
{
    __shared__ __nv_bfloat16 As[2][64 * GST];
    __shared__ __nv_bfloat16 Bs[2][64 * GST];
    int bz = blockIdx.z;
    A2 += (long long)bz * sA;
    B2 += (long long)bz * sB;
    C  += (long long)bz * sC;
    long long Ks = (long long)NC * 32;
    int m0 = blockIdx.y * 64;
    int n0 = blockIdx.x * 64;
    int tid  = threadIdx.x;
    int lane = tid & 31, warp = tid >> 5;
    int wm = warp & 1, wn = warp >> 1;       // 2 x 4
    int group = lane >> 2, tig = lane & 3;

    int lrow = tid >> 2, lcol = (tid & 3) << 3;   // one uint4 per thread per tile
    int aguard = (m0 + lrow < M);
    int bguard = (n0 + lrow < N);

    float acc[2][2][4];
#pragma unroll
    for (int i = 0; i < 2; i++)
#pragma unroll
        for (int j = 0; j < 2; j++)
#pragma unroll
            for (int q = 0; q < 4; q++) acc[i][j][q] = 0.f;

    uint4 ra = make_uint4(0,0,0,0), rb = make_uint4(0,0,0,0);
    if (aguard) ra = *(const uint4*)(A2 + (size_t)(m0 + lrow) * Ks + lcol);
    if (bguard) rb = *(const uint4*)(B2 + (size_t)(n0 + lrow) * Ks + lcol);
    *(uint4*)(As[0] + lrow * GST + lcol) = ra;
    *(uint4*)(Bs[0] + lrow * GST + lcol) = rb;
    __syncthreads();

    for (int c = 0; c < NC; c++) {
        int buf = c & 1;
        if (c + 1 < NC) {
            long long kn = (long long)(c + 1) * 32;
            if (aguard) ra = *(const uint4*)(A2 + (size_t)(m0 + lrow) * Ks + kn + lcol);
            if (bguard) rb = *(const uint4*)(B2 + (size_t)(n0 + lrow) * Ks + kn + lcol);
        }
        const __nv_bfloat16* Ab = As[buf];
        const __nv_bfloat16* Bb = Bs[buf];
#pragma unroll
        for (int ks = 0; ks < 32; ks += 16) {
            unsigned af[2][4];
#pragma unroll
            for (int mi = 0; mi < 2; mi++) {
                int r = wm * 32 + mi * 16;
                af[mi][0] = *(const unsigned*)(Ab + (r + group    ) * GST + ks + tig*2    );
                af[mi][1] = *(const unsigned*)(Ab + (r + group + 8) * GST + ks + tig*2    );
                af[mi][2] = *(const unsigned*)(Ab + (r + group    ) * GST + ks + tig*2 + 8);
                af[mi][3] = *(const unsigned*)(Ab + (r + group + 8) * GST + ks + tig*2 + 8);
            }
            unsigned bfr[2][2];
#pragma unroll
            for (int ni = 0; ni < 2; ni++) {
                int n = wn * 16 + ni * 8 + group;
                bfr[ni][0] = *(const unsigned*)(Bb + n * GST + ks + tig*2    );
                bfr[ni][1] = *(const unsigned*)(Bb + n * GST + ks + tig*2 + 8);
            }
#pragma unroll
            for (int mi = 0; mi < 2; mi++)
#pragma unroll
                for (int ni = 0; ni < 2; ni++) {
                    float* c4 = acc[mi][ni];
                    asm volatile(
                        "mma.sync.aligned.m16n8k16.row.col.f32.bf16.bf16.f32 "
                        "{%0,%1,%2,%3}, {%4,%5,%6,%7}, {%8,%9}, {%0,%1,%2,%3};\n"
                        : "+f"(c4[0]), "+f"(c4[1]), "+f"(c4[2]), "+f"(c4[3])
                        : "r"(af[mi][0]), "r"(af[mi][1]), "r"(af[mi][2]), "r"(af[mi][3]),
                          "r"(bfr[ni][0]), "r"(bfr[ni][1]));
                }
        }
        if (c + 1 < NC) {
            int nb = 1 - buf;
            *(uint4*)(As[nb] + lrow * GST + lcol) = ra;
            *(uint4*)(Bs[nb] + lrow * GST + lcol) = rb;
            __syncthreads();
        }
    }

#pragma unroll
    for (int mi = 0; mi < 2; mi++) {
        int gr = m0 + wm * 32 + mi * 16 + group;
#pragma unroll
        for (int ni = 0; ni < 2; ni++) {
            int gn = n0 + wn * 16 + ni * 8 + tig * 2;
            if (gn < N) {
                float* c4 = acc[mi][ni];
                if (gr < M)
                    *(float2*)(C + (size_t)gr * ldc + gn) = make_float2(c4[0], c4[1]);
                if (gr + 8 < M)
                    *(float2*)(C + (size_t)(gr + 8) * ldc + gn) = make_float2(c4[2], c4[3]);
            }
        }
    }
}

// ============ tensor-core vocab GEMM, double-buffered, fused exp epilogue (proven) ===
#define MBM 128
#define MBN 64
#define MKC 32
#define MST 40
#define NCHUNK 12

__global__ void __launch_bounds__(256) vocab_mma_k(
    const __nv_bfloat16* __restrict__ A2,
    const __nv_bfloat16* __restrict__ B2t,
    float* __restrict__ C,
    float* __restrict__ rsum)
{
    __shared__ __nv_bfloat16 As[2][MBM * MST];
    __shared__ __nv_bfloat16 Bs[2][MBN * MST];
    __shared__ float rowsum[MBM];
    int m0 = blockIdx.y * MBM;
    int n0 = blockIdx.x * MBN;
    int tid  = threadIdx.x;
    int lane = tid & 31, warp = tid >> 5;
    int wm = warp & 3, wn = warp >> 2;
    int group = lane >> 2, tig = lane & 3;

    int arow0 = tid >> 2,         ac0 = (tid & 3) << 3;
    int arow1 = (tid + 256) >> 2, ac1 = ac0;
    int brow  = tid >> 2,         bc  = (tid & 3) << 3;
    int bguard = (n0 + brow < V_);

    float acc[2][4][4];
#pragma unroll
    for (int i = 0; i < 2; i++)
#pragma unroll
        for (int j = 0; j < 4; j++)
#pragma unroll
            for (int q = 0; q < 4; q++) acc[i][j][q] = 0.f;

    for (int i = tid; i < MBM; i += 256) rowsum[i] = 0.f;

    uint4 ra0, ra1, rb;
    ra0 = *(const uint4*)(A2 + (size_t)(m0 + arow0) * 384 + ac0);
    ra1 = *(const uint4*)(A2 + (size_t)(m0 + arow1) * 384 + ac1);
    rb  = make_uint4(0u,0u,0u,0u);
    if (bguard) rb = *(const uint4*)(B2t + (size_t)(n0 + brow) * 384 + bc);
    *(uint4*)(As[0] + arow0 * MST + ac0) = ra0;
    *(uint4*)(As[0] + arow1 * MST + ac1) = ra1;
    *(uint4*)(Bs[0] + brow  * MST + bc ) = rb;
    __syncthreads();

    for (int c = 0; c < NCHUNK; c++) {
        int buf = c & 1;
        int kn = (c + 1) * MKC;
        if (c + 1 < NCHUNK) {
            ra0 = *(const uint4*)(A2 + (size_t)(m0 + arow0) * 384 + kn + ac0);
            ra1 = *(const uint4*)(A2 + (size_t)(m0 + arow1) * 384 + kn + ac1);
            if (bguard) rb = *(const uint4*)(B2t + (size_t)(n0 + brow) * 384 + kn + bc);
        }
        const __nv_bfloat16* Ab = As[buf];
        const __nv_bfloat16* Bb = Bs[buf];
#pragma unroll
        for (int ks = 0; ks < MKC; ks += 16) {
            unsigned af[2][4];
#pragma unroll
            for (int mi = 0; mi < 2; mi++) {
                int r = wm * 32 + mi * 16;
                af[mi][0] = *(const unsigned*)(Ab + (r + group    ) * MST + ks + tig*2    );
                af[mi][1] = *(const unsigned*)(Ab + (r + group + 8) * MST + ks + tig*2    );
                af[mi][2] = *(const unsigned*)(Ab + (r + group    ) * MST + ks + tig*2 + 8);
                af[mi][3] = *(const unsigned*)(Ab + (r + group + 8) * MST + ks + tig*2 + 8);
            }
            unsigned bfr[4][2];
#pragma unroll
            for (int ni = 0; ni < 4; ni++) {
                int n = wn * 32 + ni * 8 + group;
                bfr[ni][0] = *(const unsigned*)(Bb + n * MST + ks + tig*2    );
                bfr[ni][1] = *(const unsigned*)(Bb + n * MST + ks + tig*2 + 8);
            }
#pragma unroll
            for (int mi = 0; mi < 2; mi++)
#pragma unroll
                for (int ni = 0; ni < 4; ni++) {
                    float* c4 = acc[mi][ni];
                    asm volatile(
                        "mma.sync.aligned.m16n8k16.row.col.f32.bf16.bf16.f32 "
                        "{%0,%1,%2,%3}, {%4,%5,%6,%7}, {%8,%9}, {%0,%1,%2,%3};\n"
                        : "+f"(c4[0]), "+f"(c4[1]), "+f"(c4[2]), "+f"(c4[3])
                        : "r"(af[mi][0]), "r"(af[mi][1]), "r"(af[mi][2]), "r"(af[mi][3]),
                          "r"(bfr[ni][0]), "r"(bfr[ni][1]));
                }
        }
        if (c + 1 < NCHUNK) {
            int nb = 1 - buf;
            *(uint4*)(As[nb] + arow0 * MST + ac0) = ra0;
            *(uint4*)(As[nb] + arow1 * MST + ac1) = ra1;
            *(uint4*)(Bs[nb] + brow  * MST + bc ) = rb;
            __syncthreads();
        }
    }

#pragma unroll
    for (int mi = 0; mi < 2; mi++) {
        int rloc = wm * 32 + mi * 16 + group;
        int r = m0 + rloc;
        float psumA = 0.f, psumB = 0.f;
#pragma unroll
        for (int ni = 0; ni < 4; ni++) {
            int ccol = n0 + wn * 32 + ni * 8 + tig * 2;
            if (ccol < V_) {
                float* c4 = acc[mi][ni];
                float e0 = __expf(c4[0]), e1 = __expf(c4[1]);
                float e2 = __expf(c4[2]), e3 = __expf(c4[3]);
                *(float2*)(C + (size_t)r * V_ + ccol) = make_float2(e0, e1);
                *(float2*)(C + (size_t)(r + 8) * V_ + ccol) = make_float2(e2, e3);
                psumA += e0 + e1;
                psumB += e2 + e3;
            }
        }
        atomicAdd(&rowsum[rloc], psumA);
        atomicAdd(&rowsum[rloc + 8], psumB);
    }
    __syncthreads();
    for (int i = tid; i < MBM; i += 256) atomicAdd(&rsum[m0 + i], rowsum[i]);
}

// ---------------- intra-temporal / encnorm / dec_att / misc (proven) ---------------
__global__ void temporal_k(float* __restrict__ e)
{
    int idx = blockIdx.x * blockDim.x + threadIdx.x;
    if (idx >= B_ * (L_/4)) return;
    int b = idx / (L_/4), l4 = idx % (L_/4);
    float* base = e + (size_t)b * T_ * L_ + l4 * 4;
    float4 acc = make_float4(0.f, 0.f, 0.f, 0.f);
    for (int t = 0; t < T_; t++) {
        float4 x = *(float4*)(base + (size_t)t * L_);
        float4 ex;
        ex.x = __expf(x.x); ex.y = __expf(x.y); ex.z = __expf(x.z); ex.w = __expf(x.w);
        float4 o;
        if (t == 0) o = ex;
        else {
            o.x = ex.x / acc.x; o.y = ex.y / acc.y;
            o.z = ex.z / acc.z; o.w = ex.w / acc.w;
        }
        *(float4*)(base + (size_t)t * L_) = o;
        acc.x += ex.x; acc.y += ex.y; acc.z += ex.z; acc.w += ex.w;
    }
}

__global__ void encnorm_k(float* __restrict__ att)
{
    int r = blockIdx.x;
    float* row = att + (size_t)r * L_;
    float acc = 0.f;
    for (int i = threadIdx.x; i < L_; i += 128) acc += row[i];
    __shared__ float sh[128];
    sh[threadIdx.x] = acc;
    __syncthreads();
    for (int st = 64; st > 0; st >>= 1) {
        if (threadIdx.x < st) sh[threadIdx.x] += sh[threadIdx.x + st];
        __syncthreads();
    }
    float inv = 1.f / sh[0];
    for (int i = threadIdx.x; i < L_; i += 128) row[i] *= inv;
}

__global__ void __launch_bounds__(256) dec_att_k(
    const float* __restrict__ Xd, const float* __restrict__ dec,
    float* __restrict__ datt)
{
    int r = blockIdx.x;
    int b = r / T_, t = r % T_;
    int tid = threadIdx.x;
    float* orow = datt + (size_t)r * T_;
    if (t == 0) {
        if (tid < T_) orow[tid] = 0.f;
        return;
    }
    __shared__ float4 xs[H2_/4];
    __shared__ float sc[T_];
    for (int i = tid; i < H2_/4; i += 256)
        xs[i] = *(const float4*)(Xd + (size_t)r * H2_ + i*4);
    __syncthreads();
    int warp = tid >> 5, lane = tid & 31;
    for (int j = warp; j < t; j += 8) {
        const float4* drow = (const float4*)(dec + ((size_t)b * T_ + j) * H2_);
        float a = 0.f;
#pragma unroll
        for (int i = 0; i < H2_/128; i++) {
            float4 x = xs[lane + 32*i];
            float4 d = drow[lane + 32*i];
            a += x.x*d.x + x.y*d.y + x.z*d.z + x.w*d.w;
        }
#pragma unroll
        for (int o = 16; o > 0; o >>= 1) a += __shfl_xor_sync(0xffffffffu, a, o);
        if (lane == 0) sc[j] = a;
    }
    __syncthreads();
    if (warp == 0) {
        float v1 = (lane < t) ? sc[lane] : -1e30f;
        float v2 = (lane + 32 < t) ? sc[lane + 32] : -1e30f;
        float m = fmaxf(v1, v2);
#pragma unroll
        for (int o = 16; o > 0; o >>= 1) m = fmaxf(m, __shfl_xor_sync(0xffffffffu, m, o));
        float e1 = (lane < t) ? __expf(v1 - m) : 0.f;
        float e2 = (lane + 32 < t) ? __expf(v2 - m) : 0.f;
        float s = e1 + e2;
#pragma unroll
        for (int o = 16; o > 0; o >>= 1) s += __shfl_xor_sync(0xffffffffu, s, o);
        float inv = 1.f / s;
        if (lane < T_) orow[lane] = e1 * inv;
        if (lane + 32 < T_) orow[lane + 32] = e2 * inv;
    }
}

__global__ void copyh_k(const float* __restrict__ dec, float* __restrict__ cat)
{
    int idx = blockIdx.x * blockDim.x + threadIdx.x;
    if (idx >= BT_ * H2_) return;
    int r = idx >> 9, h = idx & 511;
    cat[(size_t)r * (3*H2_) + h] = dec[idx];
}

__global__ void pgate_k(const float* __restrict__ cat, const float* __restrict__ w,
                        const float* __restrict__ bb, float* __restrict__ p)
{
    int r = blockIdx.x;
    const float* row = cat + (size_t)r * (3*H2_);
    float acc = 0.f;
    for (int i = threadIdx.x; i < 3*H2_; i += 256) acc += row[i] * w[i];
    __shared__ float sh[256];
    sh[threadIdx.x] = acc;
    __syncthreads();
    for (int st = 128; st > 0; st >>= 1) {
        if (threadIdx.x < st) sh[threadIdx.x] += sh[threadIdx.x + st];
        __syncthreads();
    }
    if (threadIdx.x == 0) p[r] = 1.f / (1.f + __expf(-(sh[0] + bb[0])));
}

__global__ void final_k(const float* __restrict__ explogits,
                        const float* __restrict__ rsum, const float* __restrict__ p,
                        float* __restrict__ out)
{
    int r = blockIdx.y;
    int v4 = blockIdx.x * blockDim.x + threadIdx.x;
    if (v4 >= VEXT_/4) return;
    float4 o = make_float4(0.f, 0.f, 0.f, 0.f);
    if (v4 < V_/4) {
        float sc = (1.f - p[r]) / rsum[r];
        float4 x = *(const float4*)(explogits + (size_t)r * V_ + v4*4);
        o.x = sc * x.x; o.y = sc * x.y; o.z = sc * x.z; o.w = sc * x.w;
    }
    *(float4*)(out + (size_t)r * VEXT_ + v4*4) = o;
}

__global__ void scatter_k(const int* __restrict__ ev, const float* __restrict__ att,
                          const float* __restrict__ p, float* __restrict__ out)
{
    int idx = blockIdx.x * blockDim.x + threadIdx.x;
    if (idx >= BT_ * L_) return;
    int l = idx % L_;
    int r = idx / L_;
    int b = r / T_;
    float val = p[r] * att[idx];
    atomicAdd(&out[(size_t)r * VEXT_ + ev[b * L_ + l]], val);
}

// ---------------- host orchestration ----------------
static void gemm(int M, int N, int K,
                 const float* A, int lda, long long sA,
                 const float* B, int ldb, long long sB, int transB,
                 float* C, int ldc, long long sC, int batch)
{
    dim3 grid((N + TN - 1) / TN, (M + TM - 1) / TM, batch);
    gemm_k<<<grid, 256>>>(M, N, K, A, lda, sA, B, ldb, sB, transB, C, ldc, sC);
}

static void gmma(int M, int N, int K,
                 const __nv_bfloat16* A2, long long sA,
                 const __nv_bfloat16* B2, long long sB,
                 float* C, int ldc, long long sC, int batch)
{
    dim3 grid((N + 63) / 64, (M + 63) / 64, batch);
    gmma_k<<<grid, 256>>>(M, N, (3 * K) / 32, A2, sA, B2, sB, C, ldc, sC);
}

extern "C" void kernel_launch(void* const* d_in, const int* in_sizes, int n_in,
                              void* d_out, int out_size)
{
    const float* dec     = (const float*)d_in[0];
    const float* enc     = (const float*)d_in[1];
    const float* W_enc   = (const float*)d_in[2];
    const float* W_dec   = (const float*)d_in[3];
    const float* W_proj  = (const float*)d_in[4];
    const float* W_vocab = (const float*)d_in[5];
    const float* w_ptr   = (const float*)d_in[6];
    const float* b_ptr   = (const float*)d_in[7];
    const int*   ev      = (const int*)d_in[8];
    float* out = (float*)d_out;

    float *Xe, *Xd, *att, *s, *cat, *proj, *p, *rsum, *logits;
    __nv_bfloat16 *A2, *B2t, *dec2, *Xe2, *enc2, *cat2, *Wenc2t, *Wdec2t, *Wproj2t;
    cudaGetSymbolAddress((void**)&Xe,     g_Xe);
    cudaGetSymbolAddress((void**)&Xd,     g_Xd);
    cudaGetSymbolAddress((void**)&att,    g_att);
    cudaGetSymbolAddress((void**)&s,      g_s);
    cudaGetSymbolAddress((void**)&cat,    g_cat);
    cudaGetSymbolAddress((void**)&proj,   g_proj);
    cudaGetSymbolAddress((void**)&p,      g_p);
    cudaGetSymbolAddress((void**)&rsum,   g_rsum);
    cudaGetSymbolAddress((void**)&logits, g_logits);
    cudaGetSymbolAddress((void**)&A2,     g_A2);
    cudaGetSymbolAddress((void**)&B2t,    g_B2t);
    cudaGetSymbolAddress((void**)&dec2,   g_dec2);
    cudaGetSymbolAddress((void**)&Xe2,    g_Xe2);
    cudaGetSymbolAddress((void**)&enc2,   g_enc2);
    cudaGetSymbolAddress((void**)&cat2,   g_cat2);
    cudaGetSymbolAddress((void**)&Wenc2t, g_Wenc2t);
    cudaGetSymbolAddress((void**)&Wdec2t, g_Wdec2t);
    cudaGetSymbolAddress((void**)&Wproj2t,g_Wproj2t);

    // 0) weight/activation conversions (independent prep)
    convB_k<<<(V_ + 63) / 64, 256>>>(W_vocab, B2t);
    zero_rsum_k<<<(BT_ + 255)/256, 256>>>(rsum);
    transsplit_k<<<dim3(8, 8), 256>>>(W_enc, Wenc2t, H2_, H2_);
    transsplit_k<<<dim3(8, 8), 256>>>(W_dec, Wdec2t, H2_, H2_);
    transsplit_k<<<dim3(2, 24), 256>>>(W_proj, Wproj2t, 3*H2_, E_);
    split_k<<<(BT_*H2_ + 255)/256, 256>>>(dec, dec2, BT_, H2_, 0);
    split_k<<<(B_*L_*H2_ + 255)/256, 256>>>(enc, enc2, B_*L_, H2_, 1);

    // 1) bilinear projections via MMA
    gmma(BT_, H2_, H2_, dec2, 0, Wenc2t, 0, Xe, H2_, 0, 1);
    gmma(BT_, H2_, H2_, dec2, 0, Wdec2t, 0, Xd, H2_, 0, 1);

    // 2) encoder attention scores via batched MMA
    split_k<<<(BT_*H2_ + 255)/256, 256>>>(Xe, Xe2, BT_, H2_, 0);
    gmma(T_, L_, H2_, Xe2, (long long)T_*3*H2_, enc2, (long long)L_*3*H2_,
         att, L_, (long long)T_*L_, B_);

    // 3) intra-temporal + normalize
    temporal_k<<<(B_*(L_/4) + 255)/256, 256>>>(att);
    encnorm_k<<<BT_, 128>>>(att);

    // 4) fused decoder self-attention
    dec_att_k<<<BT_, 256>>>(Xd, dec, s);

    // 5) assemble cat = [h | enc_ctx | dec_ctx]  (ctx GEMMs stay fp32: K=400/48)
    copyh_k<<<(BT_*H2_ + 255)/256, 256>>>(dec, cat);
    gemm(T_, H2_, L_, att, L_, (long long)T_*L_,
         enc, H2_, (long long)L_*H2_, 0,
         cat + H2_, 3*H2_, (long long)T_*3*H2_, B_);
    gemm(T_, H2_, T_, s, T_, (long long)T_*T_,
         dec, H2_, (long long)T_*H2_, 0,
         cat + 2*H2_, 3*H2_, (long long)T_*3*H2_, B_);

    // 6) copy gate + embedding projection via MMA
    pgate_k<<<BT_, 256>>>(cat, w_ptr, b_ptr, p);
    split_k<<<(BT_*3*H2_ + 255)/256, 256>>>(cat, cat2, BT_, 3*H2_, 0);
    gmma(BT_, E_, 3*H2_, cat2, 0, Wproj2t, 0, proj, E_, 0, 1);

    // 7) vocab logits via tensor cores (fused exp + row-sum epilogue)
    convA_k<<<(BT_*E_ + 255)/256, 256>>>(proj, A2);
    {
        dim3 grid((V_ + MBN - 1) / MBN, BT_ / MBM);
        vocab_mma_k<<<grid, 256>>>(A2, B2t, logits, rsum);
    }

    // 8) final distribution write + pointer scatter
    final_k<<<dim3((VEXT_/4 + 255)/256, BT_), 256>>>(logits, rsum, p, out);
    scatter_k<<<(BT_*L_ + 255)/256, 256>>>(ev, att, p, out);
}

// round 15
// speedup vs baseline: 1.5148x; 1.0527x over previous
#include <cuda_runtime.h>
#include <cuda_bf16.h>
#include <math.h>

#define B_   32
#define T_   48
#define L_   400
#define H2_  512
#define E_   128
#define V_   50000
#define OOV_ 100
#define VEXT_ 50100
#define BT_  (B_*T_)

// ldmatrix x4: loads 4 8x8 b16 matrices; thread t supplies row (t&7) of matrix (t>>3).
// Output distribution per matrix: thread t holds (row = t>>2, cols = 2*(t&3)+{0,1}).
#define LDSM4(r0, r1, r2, r3, addr) \
    asm volatile("ldmatrix.sync.aligned.m8n8.x4.shared.b16 {%0,%1,%2,%3}, [%4];" \
        : "=r"(r0), "=r"(r1), "=r"(r2), "=r"(r3) : "r"(addr))

// ---------------- scratch (static device allocations; no cudaMalloc) ----------------
__device__ float g_Xe[BT_*H2_];
__device__ float g_Xd[BT_*H2_];
__device__ float g_att[BT_*L_];
__device__ float g_s[BT_*T_];
__device__ float g_cat[BT_*3*H2_];
__device__ float g_proj[BT_*E_];
__device__ float g_p[BT_];
__device__ float g_rsum[BT_];
__device__ float g_logits[(size_t)BT_*V_];            // exp(logits), 307 MB
__device__ __nv_bfloat16 g_A2[(size_t)BT_*3*E_];      // vocab A split (BT,384)
__device__ __nv_bfloat16 g_B2t[(size_t)V_*3*E_];      // vocab B^T split (V,384)
__device__ __nv_bfloat16 g_dec2 [(size_t)BT_*3*H2_];
__device__ __nv_bfloat16 g_Xe2  [(size_t)BT_*3*H2_];
__device__ __nv_bfloat16 g_enc2 [(size_t)B_*L_*3*H2_];
__device__ __nv_bfloat16 g_cat2 [(size_t)BT_*9*H2_];
__device__ __nv_bfloat16 g_Wenc2t[(size_t)H2_*3*H2_];
__device__ __nv_bfloat16 g_Wdec2t[(size_t)H2_*3*H2_];
__device__ __nv_bfloat16 g_Wproj2t[(size_t)E_*9*H2_];

// ---------------- generic tiled fp32 GEMM with register prefetch (proven) ----------
#define TM 64
#define TN 64
#define TKK 16

__global__ void gemm_k(int M, int N, int K,
                       const float* __restrict__ A, int lda, long long sA,
                       const float* __restrict__ B, int ldb, long long sB, int transB,
                       float* __restrict__ C, int ldc, long long sC)
{
    __shared__ float As[TKK][TM];
    __shared__ float Bs[TKK][TN];
    int bz = blockIdx.z;
    A += (long long)bz * sA;
    B += (long long)bz * sB;
    C += (long long)bz * sC;
    int m0 = blockIdx.y * TM;
    int n0 = blockIdx.x * TN;
    int tid = threadIdx.x;
    int tx = tid & 15, ty = tid >> 4;
    float acc[4][4] = {};
    float ar[4], br[4];

#pragma unroll
    for (int i = 0; i < 4; i++) {
        int li = tid + 256 * i;
        int m = li & 63, k = li >> 6;
        int gm = m0 + m, gk = k;
        ar[i] = (gm < M && gk < K) ? A[(long long)gm * lda + gk] : 0.f;
    }
#pragma unroll
    for (int i = 0; i < 4; i++) {
        int li = tid + 256 * i;
        int n = li & 63, k = li >> 6;
        int gn = n0 + n, gk = k;
        float v = 0.f;
        if (gn < N && gk < K)
            v = transB ? B[(long long)gn * ldb + gk] : B[(long long)gk * ldb + gn];
        br[i] = v;
    }

    for (int kk = 0; kk < K; kk += TKK) {
#pragma unroll
        for (int i = 0; i < 4; i++) { int li = tid + 256*i; As[li>>6][li&63] = ar[i]; }
#pragma unroll
        for (int i = 0; i < 4; i++) { int li = tid + 256*i; Bs[li>>6][li&63] = br[i]; }
        __syncthreads();

        int kn = kk + TKK;
        if (kn < K) {
#pragma unroll
            for (int i = 0; i < 4; i++) {
                int li = tid + 256 * i;
                int m = li & 63, k = li >> 6;
                int gm = m0 + m, gk = kn + k;
                ar[i] = (gm < M && gk < K) ? A[(long long)gm * lda + gk] : 0.f;
            }
#pragma unroll
            for (int i = 0; i < 4; i++) {
                int li = tid + 256 * i;
                int n = li & 63, k = li >> 6;
                int gn = n0 + n, gk = kn + k;
                float v = 0.f;
                if (gn < N && gk < K)
                    v = transB ? B[(long long)gn * ldb + gk] : B[(long long)gk * ldb + gn];
                br[i] = v;
            }
        }

#pragma unroll
        for (int k = 0; k < TKK; k++) {
            float a0[4], b0[4];
#pragma unroll
            for (int i = 0; i < 4; i++) a0[i] = As[k][ty*4 + i];
#pragma unroll
            for (int j = 0; j < 4; j++) b0[j] = Bs[k][tx*4 + j];
#pragma unroll
            for (int i = 0; i < 4; i++)
#pragma unroll
                for (int j = 0; j < 4; j++)
                    acc[i][j] = fmaf(a0[i], b0[j], acc[i][j]);
        }
        __syncthreads();
    }
#pragma unroll
    for (int i = 0; i < 4; i++) {
        int gm = m0 + ty*4 + i;
        if (gm >= M) continue;
#pragma unroll
        for (int j = 0; j < 4; j++) {
            int gn = n0 + tx*4 + j;
            if (gn < N) C[(long long)gm * ldc + gn] = acc[i][j];
        }
    }
}

// ============ split-bf16 conversion kernels ============
__global__ void split_k(const float* __restrict__ src, __nv_bfloat16* __restrict__ dst,
                        int R, int K, int bmode)
{
    int idx = blockIdx.x * blockDim.x + threadIdx.x;
    if (idx >= R * K) return;
    int r = idx / K, k = idx - r * K;
    float x = src[idx];
    __nv_bfloat16 hi = __float2bfloat16(x);
    __nv_bfloat16 lo = __float2bfloat16(x - __bfloat162float(hi));
    __nv_bfloat16* row = dst + (size_t)r * 3 * K;
    row[k] = hi;
    if (bmode) { row[K + k] = lo; row[2*K + k] = hi; }
    else       { row[K + k] = hi; row[2*K + k] = lo; }
}

// transpose + split, 32x32 tiles (high block count -> latency-tolerant)
__global__ void transsplit_k(const float* __restrict__ src, __nv_bfloat16* __restrict__ dst,
                             int K, int N)
{
    __shared__ float sh[32][33];
    int n0 = blockIdx.x * 32;
    int k0 = blockIdx.y * 32;
    int tid = threadIdx.x;
    for (int idx = tid; idx < 32*32; idx += 256) {
        int kk = idx >> 5, nn = idx & 31;
        float v = 0.f;
        if (k0 + kk < K && n0 + nn < N) v = src[(size_t)(k0 + kk) * N + n0 + nn];
        sh[kk][nn] = v;
    }
    __syncthreads();
    for (int idx = tid; idx < 32*32; idx += 256) {
        int nn = idx >> 5, kk = idx & 31;
        if (n0 + nn >= N || k0 + kk >= K) continue;
        float x = sh[kk][nn];
        __nv_bfloat16 hi = __float2bfloat16(x);
        __nv_bfloat16 lo = __float2bfloat16(x - __bfloat162float(hi));
        __nv_bfloat16* row = dst + (size_t)(n0 + nn) * 3 * K;
        row[k0 + kk]       = hi;
        row[K + k0 + kk]   = lo;
        row[2*K + k0 + kk] = hi;
    }
}

__global__ void convA_k(const float* __restrict__ proj, __nv_bfloat16* __restrict__ A2)
{
    int idx = blockIdx.x * blockDim.x + threadIdx.x;
    if (idx >= BT_ * E_) return;
    int r = idx >> 7, k = idx & 127;
    float x = proj[idx];
    __nv_bfloat16 hi = __float2bfloat16(x);
    __nv_bfloat16 lo = __float2bfloat16(x - __bfloat162float(hi));
    __nv_bfloat16* row = A2 + (size_t)r * 384;
    row[k]       = hi;
    row[128 + k] = hi;
    row[256 + k] = lo;
}

__global__ void convB_k(const float* __restrict__ Wv, __nv_bfloat16* __restrict__ B2t)
{
    __shared__ float sh[128][65];
    int n0 = blockIdx.x * 64;
    int tid = threadIdx.x;
    for (int idx = tid; idx < 128 * 64; idx += 256) {
        int k = idx >> 6, n = idx & 63;
        float v = 0.f;
        if (n0 + n < V_) v = Wv[(size_t)k * V_ + n0 + n];
        sh[k][n] = v;
    }
    __syncthreads();
    for (int idx = tid; idx < 64 * 128; idx += 256) {
        int n = idx >> 7, k = idx & 127;
        if (n0 + n >= V_) continue;
        float x = sh[k][n];
        __nv_bfloat16 hi = __float2bfloat16(x);
        __nv_bfloat16 lo = __float2bfloat16(x - __bfloat162float(hi));
        __nv_bfloat16* row = B2t + (size_t)(n0 + n) * 384;
        row[k]       = hi;
        row[128 + k] = lo;
        row[256 + k] = hi;
    }
}

__global__ void zero_rsum_k(float* __restrict__ rsum)
{
    int i = blockIdx.x * blockDim.x + threadIdx.x;
    if (i < BT_) rsum[i] = 0.f;
}

// ============ generic batched split-bf16 MMA GEMM (ldmatrix fragments) ============
#define GST 40

__global__ void __launch_bounds__(256) gmma_k(
    int M, int N, int NC,
    const __nv_bfloat16* __restrict__ A2, long long sA,
    const __nv_bfloat16* __restrict__ B2, long long sB,
    float* __restrict__ C, int ldc, long long sC)
{
    __shared__ __nv_bfloat16 As[2][64 * GST];
    __shared__ __nv_bfloat16 Bs[2][64 * GST];
    int bz = blockIdx.z;
    A2 += (long long)bz * sA;
    B2 += (long long)bz * sB;
    C  += (long long)bz * sC;
    long long Ks = (long long)NC * 32;
    int m0 = blockIdx.y * 64;
    int n0 = blockIdx.x * 64;
    int tid  = threadIdx.x;
    int lane = tid & 31, warp = tid >> 5;
    int wm = warp & 1, wn = warp >> 1;
    int group = lane >> 2, tig = lane & 3;

    int lrow = tid >> 2, lcol = (tid & 3) << 3;
    int aguard = (m0 + lrow < M);
    int bguard = (n0 + lrow < N);

    // ldmatrix per-thread source row/col-half (same for A and B matrices)
    int lm_mat = lane >> 3, lm_r = lane & 7;
    int lm_rowoff = (lm_mat & 1) * 8 + lm_r;   // row within 16-row fragment
    int lm_koff   = (lm_mat >> 1) * 8;         // k-half offset

    float acc[2][2][4];
#pragma unroll
    for (int i = 0; i < 2; i++)
#pragma unroll
        for (int j = 0; j < 2; j++)
#pragma unroll
            for (int q = 0; q < 4; q++) acc[i][j][q] = 0.f;

    uint4 ra = make_uint4(0,0,0,0), rb = make_uint4(0,0,0,0);
    if (aguard) ra = *(const uint4*)(A2 + (size_t)(m0 + lrow) * Ks + lcol);
    if (bguard) rb = *(const uint4*)(B2 + (size_t)(n0 + lrow) * Ks + lcol);
    *(uint4*)(As[0] + lrow * GST + lcol) = ra;
    *(uint4*)(Bs[0] + lrow * GST + lcol) = rb;
    __syncthreads();

    for (int c = 0; c < NC; c++) {
        int buf = c & 1;
        if (c + 1 < NC) {
            long long kn = (long long)(c + 1) * 32;
            if (aguard) ra = *(const uint4*)(A2 + (size_t)(m0 + lrow) * Ks + kn + lcol);
            if (bguard) rb = *(const uint4*)(B2 + (size_t)(n0 + lrow) * Ks + kn + lcol);
        }
        unsigned abase = (unsigned)__cvta_generic_to_shared(As[buf]);
        unsigned bbase = (unsigned)__cvta_generic_to_shared(Bs[buf]);
#pragma unroll
        for (int ks = 0; ks < 32; ks += 16) {
            unsigned af[2][4];
#pragma unroll
            for (int mi = 0; mi < 2; mi++) {
                unsigned aaddr = abase +
                    (unsigned)(((wm*32 + mi*16 + lm_rowoff) * GST + ks + lm_koff) * 2);
                LDSM4(af[mi][0], af[mi][1], af[mi][2], af[mi][3], aaddr);
            }
            unsigned bfr[2][2];
            {
                // mats: (ni0,k0),(ni0,k8),(ni1,k0),(ni1,k8)
                int bni = lm_mat >> 1, bkh = (lm_mat & 1) * 8;
                unsigned baddr = bbase +
                    (unsigned)(((wn*16 + bni*8 + lm_r) * GST + ks + bkh) * 2);
                LDSM4(bfr[0][0], bfr[0][1], bfr[1][0], bfr[1][1], baddr);
            }
#pragma unroll
            for (int mi = 0; mi < 2; mi++)
#pragma unroll
                for (int ni = 0; ni < 2; ni++) {
                    float* c4 = acc[mi][ni];
                    asm volatile(
                        "mma.sync.aligned.m16n8k16.row.col.f32.bf16.bf16.f32 "
                        "{%0,%1,%2,%3}, {%4,%5,%6,%7}, {%8,%9}, {%0,%1,%2,%3};\n"
                        : "+f"(c4[0]), "+f"(c4[1]), "+f"(c4[2]), "+f"(c4[3])
                        : "r"(af[mi][0]), "r"(af[mi][1]), "r"(af[mi][2]), "r"(af[mi][3]),
                          "r"(bfr[ni][0]), "r"(bfr[ni][1]));
                }
        }
        if (c + 1 < NC) {
            int nb = 1 - buf;
            *(uint4*)(As[nb] + lrow * GST + lcol) = ra;
            *(uint4*)(Bs[nb] + lrow * GST + lcol) = rb;
            __syncthreads();
        }
    }

#pragma unroll
    for (int mi = 0; mi < 2; mi++) {
        int gr = m0 + wm * 32 + mi * 16 + group;
#pragma unroll
        for (int ni = 0; ni < 2; ni++) {
            int gn = n0 + wn * 16 + ni * 8 + tig * 2;
            if (gn < N) {
                float* c4 = acc[mi][ni];
                if (gr < M)
                    *(float2*)(C + (size_t)gr * ldc + gn) = make_float2(c4[0], c4[1]);
                if (gr + 8 < M)
                    *(float2*)(C + (size_t)(gr + 8) * ldc + gn) = make_float2(c4[2], c4[3]);
            }
        }
    }
}

// ============ tensor-core vocab GEMM, ldmatrix + fused exp epilogue ============
#define MBM 128
#define MBN 64
#define MKC 32
#define MST 40
#define NCHUNK 12

__global__ void __launch_bounds__(256) vocab_mma_k(
    const __nv_bfloat16* __restrict__ A2,
    const __nv_bfloat16* __restrict__ B2t,
    float* __restrict__ C,
    float* __restrict__ rsum)
{
    __shared__ __nv_bfloat16 As[2][MBM * MST];
    __shared__ __nv_bfloat16 Bs[2][MBN * MST];
    __shared__ float rowsum[MBM];
    int m0 = blockIdx.y * MBM;
    int n0 = blockIdx.x * MBN;
    int tid  = threadIdx.x;
    int lane = tid & 31, warp = tid >> 5;
    int wm = warp & 3, wn = warp >> 2;
    int group = lane >> 2, tig = lane & 3;

    int arow0 = tid >> 2,         ac0 = (tid & 3) << 3;
    int arow1 = (tid + 256) >> 2, ac1 = ac0;
    int brow  = tid >> 2,         bc  = (tid & 3) << 3;
    int bguard = (n0 + brow < V_);

    int lm_mat = lane >> 3, lm_r = lane & 7;
    int lm_rowoff = (lm_mat & 1) * 8 + lm_r;
    int lm_koff   = (lm_mat >> 1) * 8;
    int bni = lm_mat >> 1, bkh = (lm_mat & 1) * 8;

    float acc[2][4][4];
#pragma unroll
    for (int i = 0; i < 2; i++)
#pragma unroll
        for (int j = 0; j < 4; j++)
#pragma unroll
            for (int q = 0; q < 4; q++) acc[i][j][q] = 0.f;

    for (int i = tid; i < MBM; i += 256) rowsum[i] = 0.f;

    uint4 ra0, ra1, rb;
    ra0 = *(const uint4*)(A2 + (size_t)(m0 + arow0) * 384 + ac0);
    ra1 = *(const uint4*)(A2 + (size_t)(m0 + arow1) * 384 + ac1);
    rb  = make_uint4(0u,0u,0u,0u);
    if (bguard) rb = *(const uint4*)(B2t + (size_t)(n0 + brow) * 384 + bc);
    *(uint4*)(As[0] + arow0 * MST + ac0) = ra0;
    *(uint4*)(As[0] + arow1 * MST + ac1) = ra1;
    *(uint4*)(Bs[0] + brow  * MST + bc ) = rb;
    __syncthreads();

    for (int c = 0; c < NCHUNK; c++) {
        int buf = c & 1;
        int kn = (c + 1) * MKC;
        if (c + 1 < NCHUNK) {
            ra0 = *(const uint4*)(A2 + (size_t)(m0 + arow0) * 384 + kn + ac0);
            ra1 = *(const uint4*)(A2 + (size_t)(m0 + arow1) * 384 + kn + ac1);
            if (bguard) rb = *(const uint4*)(B2t + (size_t)(n0 + brow) * 384 + kn + bc);
        }
        unsigned abase = (unsigned)__cvta_generic_to_shared(As[buf]);
        unsigned bbase = (unsigned)__cvta_generic_to_shared(Bs[buf]);
#pragma unroll
        for (int ks = 0; ks < MKC; ks += 16) {
            unsigned af[2][4];
#pragma unroll
            for (int mi = 0; mi < 2; mi++) {
                unsigned aaddr = abase +
                    (unsigned)(((wm*32 + mi*16 + lm_rowoff) * MST + ks + lm_koff) * 2);
                LDSM4(af[mi][0], af[mi][1], af[mi][2], af[mi][3], aaddr);
            }
            unsigned bfr[4][2];
            {
                unsigned baddr = bbase +
                    (unsigned)(((wn*32 + bni*8 + lm_r) * MST + ks + bkh) * 2);
                LDSM4(bfr[0][0], bfr[0][1], bfr[1][0], bfr[1][1], baddr);
                LDSM4(bfr[2][0], bfr[2][1], bfr[3][0], bfr[3][1],
                      baddr + (unsigned)(16 * MST * 2));
            }
#pragma unroll
            for (int mi = 0; mi < 2; mi++)
#pragma unroll
                for (int ni = 0; ni < 4; ni++) {
                    float* c4 = acc[mi][ni];
                    asm volatile(
                        "mma.sync.aligned.m16n8k16.row.col.f32.bf16.bf16.f32 "
                        "{%0,%1,%2,%3}, {%4,%5,%6,%7}, {%8,%9}, {%0,%1,%2,%3};\n"
                        : "+f"(c4[0]), "+f"(c4[1]), "+f"(c4[2]), "+f"(c4[3])
                        : "r"(af[mi][0]), "r"(af[mi][1]), "r"(af[mi][2]), "r"(af[mi][3]),
                          "r"(bfr[ni][0]), "r"(bfr[ni][1]));
                }
        }
        if (c + 1 < NCHUNK) {
            int nb = 1 - buf;
            *(uint4*)(As[nb] + arow0 * MST + ac0) = ra0;
            *(uint4*)(As[nb] + arow1 * MST + ac1) = ra1;
            *(uint4*)(Bs[nb] + brow  * MST + bc ) = rb;
            __syncthreads();
        }
    }

#pragma unroll
    for (int mi = 0; mi < 2; mi++) {
        int rloc = wm * 32 + mi * 16 + group;
        int r = m0 + rloc;
        float psumA = 0.f, psumB = 0.f;
#pragma unroll
        for (int ni = 0; ni < 4; ni++) {
            int ccol = n0 + wn * 32 + ni * 8 + tig * 2;
            if (ccol < V_) {
                float* c4 = acc[mi][ni];
                float e0 = __expf(c4[0]), e1 = __expf(c4[1]);
                float e2 = __expf(c4[2]), e3 = __expf(c4[3]);
                *(float2*)(C + (size_t)r * V_ + ccol) = make_float2(e0, e1);
                *(float2*)(C + (size_t)(r + 8) * V_ + ccol) = make_float2(e2, e3);
                psumA += e0 + e1;
                psumB += e2 + e3;
            }
        }
        atomicAdd(&rowsum[rloc], psumA);
        atomicAdd(&rowsum[rloc + 8], psumB);
    }
    __syncthreads();
    for (int i = tid; i < MBM; i += 256) atomicAdd(&rsum[m0 + i], rowsum[i]);
}

// ---------------- pointwise / attention kernels (proven) ----------------
__global__ void temporal_k(float* __restrict__ e)
{
    int idx = blockIdx.x * blockDim.x + threadIdx.x;
    if (idx >= B_ * (L_/4)) return;
    int b = idx / (L_/4), l4 = idx % (L_/4);
    float* base = e + (size_t)b * T_ * L_ + l4 * 4;
    float4 acc = make_float4(0.f, 0.f, 0.f, 0.f);
    for (int t = 0; t < T_; t++) {
        float4 x = *(float4*)(base + (size_t)t * L_);
        float4 ex;
        ex.x = __expf(x.x); ex.y = __expf(x.y); ex.z = __expf(x.z); ex.w = __expf(x.w);
        float4 o;
        if (t == 0) o = ex;
        else {
            o.x = ex.x / acc.x; o.y = ex.y / acc.y;
            o.z = ex.z / acc.z; o.w = ex.w / acc.w;
        }
        *(float4*)(base + (size_t)t * L_) = o;
        acc.x += ex.x; acc.y += ex.y; acc.z += ex.z; acc.w += ex.w;
    }
}

__global__ void encnorm_k(float* __restrict__ att)
{
    int r = blockIdx.x;
    float* row = att + (size_t)r * L_;
    float acc = 0.f;
    for (int i = threadIdx.x; i < L_; i += 128) acc += row[i];
    __shared__ float sh[128];
    sh[threadIdx.x] = acc;
    __syncthreads();
    for (int st = 64; st > 0; st >>= 1) {
        if (threadIdx.x < st) sh[threadIdx.x] += sh[threadIdx.x + st];
        __syncthreads();
    }
    float inv = 1.f / sh[0];
    for (int i = threadIdx.x; i < L_; i += 128) row[i] *= inv;
}

__global__ void __launch_bounds__(256) dec_att_k(
    const float* __restrict__ Xd, const float* __restrict__ dec,
    float* __restrict__ datt)
{
    int r = blockIdx.x;
    int b = r / T_, t = r % T_;
    int tid = threadIdx.x;
    float* orow = datt + (size_t)r * T_;
    if (t == 0) {
        if (tid < T_) orow[tid] = 0.f;
        return;
    }
    __shared__ float4 xs[H2_/4];
    __shared__ float sc[T_];
    for (int i = tid; i < H2_/4; i += 256)
        xs[i] = *(const float4*)(Xd + (size_t)r * H2_ + i*4);
    __syncthreads();
    int warp = tid >> 5, lane = tid & 31;
    for (int j = warp; j < t; j += 8) {
        const float4* drow = (const float4*)(dec + ((size_t)b * T_ + j) * H2_);
        float a = 0.f;
#pragma unroll
        for (int i = 0; i < H2_/128; i++) {
            float4 x = xs[lane + 32*i];
            float4 d = drow[lane + 32*i];
            a += x.x*d.x + x.y*d.y + x.z*d.z + x.w*d.w;
        }
#pragma unroll
        for (int o = 16; o > 0; o >>= 1) a += __shfl_xor_sync(0xffffffffu, a, o);
        if (lane == 0) sc[j] = a;
    }
    __syncthreads();
    if (warp == 0) {
        float v1 = (lane < t) ? sc[lane] : -1e30f;
        float v2 = (lane + 32 < t) ? sc[lane + 32] : -1e30f;
        float m = fmaxf(v1, v2);
#pragma unroll
        for (int o = 16; o > 0; o >>= 1) m = fmaxf(m, __shfl_xor_sync(0xffffffffu, m, o));
        float e1 = (lane < t) ? __expf(v1 - m) : 0.f;
        float e2 = (lane + 32 < t) ? __expf(v2 - m) : 0.f;
        float s = e1 + e2;
#pragma unroll
        for (int o = 16; o > 0; o >>= 1) s += __shfl_xor_sync(0xffffffffu, s, o);
        float inv = 1.f / s;
        if (lane < T_) orow[lane] = e1 * inv;
        if (lane + 32 < T_) orow[lane + 32] = e2 * inv;
    }
}

__global__ void copyh_k(const float* __restrict__ dec, float* __restrict__ cat)
{
    int idx = blockIdx.x * blockDim.x + threadIdx.x;
    if (idx >= BT_ * H2_) return;
    int r = idx >> 9, h = idx & 511;
    cat[(size_t)r * (3*H2_) + h] = dec[idx];
}

__global__ void pgate_k(const float* __restrict__ cat, const float* __restrict__ w,
                        const float* __restrict__ bb, float* __restrict__ p)
{
    int r = blockIdx.x;
    const float* row = cat + (size_t)r * (3*H2_);
    float acc = 0.f;
    for (int i = threadIdx.x; i < 3*H2_; i += 256) acc += row[i] * w[i];
    __shared__ float sh[256];
    sh[threadIdx.x] = acc;
    __syncthreads();
    for (int st = 128; st > 0; st >>= 1) {
        if (threadIdx.x < st) sh[threadIdx.x] += sh[threadIdx.x + st];
        __syncthreads();
    }
    if (threadIdx.x == 0) p[r] = 1.f / (1.f + __expf(-(sh[0] + bb[0])));
}

__global__ void final_k(const float* __restrict__ explogits,
                        const float* __restrict__ rsum, const float* __restrict__ p,
                        float* __restrict__ out)
{
    int r = blockIdx.y;
    int v4 = blockIdx.x * blockDim.x + threadIdx.x;
    if (v4 >= VEXT_/4) return;
    float4 o = make_float4(0.f, 0.f, 0.f, 0.f);
    if (v4 < V_/4) {
        float sc = (1.f - p[r]) / rsum[r];
        float4 x = *(const float4*)(explogits + (size_t)r * V_ + v4*4);
        o.x = sc * x.x; o.y = sc * x.y; o.z = sc * x.z; o.w = sc * x.w;
    }
    *(float4*)(out + (size_t)r * VEXT_ + v4*4) = o;
}

__global__ void scatter_k(const int* __restrict__ ev, const float* __restrict__ att,
                          const float* __restrict__ p, float* __restrict__ out)
{
    int idx = blockIdx.x * blockDim.x + threadIdx.x;
    if (idx >= BT_ * L_) return;
    int l = idx % L_;
    int r = idx / L_;
    int b = r / T_;
    float val = p[r] * att[idx];
    atomicAdd(&out[(size_t)r * VEXT_ + ev[b * L_ + l]], val);
}

// ---------------- host orchestration ----------------
static void gemm(int M, int N, int K,
                 const float* A, int lda, long long sA,
                 const float* B, int ldb, long long sB, int transB,
                 float* C, int ldc, long long sC, int batch)
{
    dim3 grid((N + TN - 1) / TN, (M + TM - 1) / TM, batch);
    gemm_k<<<grid, 256>>>(M, N, K, A, lda, sA, B, ldb, sB, transB, C, ldc, sC);
}

static void gmma(int M, int N, int K,
                 const __nv_bfloat16* A2, long long sA,
                 const __nv_bfloat16* B2, long long sB,
                 float* C, int ldc, long long sC, int batch)
{
    dim3 grid((N + 63) / 64, (M + 63) / 64, batch);
    gmma_k<<<grid, 256>>>(M, N, (3 * K) / 32, A2, sA, B2, sB, C, ldc, sC);
}

extern "C" void kernel_launch(void* const* d_in, const int* in_sizes, int n_in,
                              void* d_out, int out_size)
{
    const float* dec     = (const float*)d_in[0];
    const float* enc     = (const float*)d_in[1];
    const float* W_enc   = (const float*)d_in[2];
    const float* W_dec   = (const float*)d_in[3];
    const float* W_proj  = (const float*)d_in[4];
    const float* W_vocab = (const float*)d_in[5];
    const float* w_ptr   = (const float*)d_in[6];
    const float* b_ptr   = (const float*)d_in[7];
    const int*   ev      = (const int*)d_in[8];
    float* out = (float*)d_out;

    float *Xe, *Xd, *att, *s, *cat, *proj, *p, *rsum, *logits;
    __nv_bfloat16 *A2, *B2t, *dec2, *Xe2, *enc2, *cat2, *Wenc2t, *Wdec2t, *Wproj2t;
    cudaGetSymbolAddress((void**)&Xe,     g_Xe);
    cudaGetSymbolAddress((void**)&Xd,     g_Xd);
    cudaGetSymbolAddress((void**)&att,    g_att);
    cudaGetSymbolAddress((void**)&s,      g_s);
    cudaGetSymbolAddress((void**)&cat,    g_cat);
    cudaGetSymbolAddress((void**)&proj,   g_proj);
    cudaGetSymbolAddress((void**)&p,      g_p);
    cudaGetSymbolAddress((void**)&rsum,   g_rsum);
    cudaGetSymbolAddress((void**)&logits, g_logits);
    cudaGetSymbolAddress((void**)&A2,     g_A2);
    cudaGetSymbolAddress((void**)&B2t,    g_B2t);
    cudaGetSymbolAddress((void**)&dec2,   g_dec2);
    cudaGetSymbolAddress((void**)&Xe2,    g_Xe2);
    cudaGetSymbolAddress((void**)&enc2,   g_enc2);
    cudaGetSymbolAddress((void**)&cat2,   g_cat2);
    cudaGetSymbolAddress((void**)&Wenc2t, g_Wenc2t);
    cudaGetSymbolAddress((void**)&Wdec2t, g_Wdec2t);
    cudaGetSymbolAddress((void**)&Wproj2t,g_Wproj2t);

    // 0) weight/activation conversions
    convB_k<<<(V_ + 63) / 64, 256>>>(W_vocab, B2t);
    zero_rsum_k<<<(BT_ + 255)/256, 256>>>(rsum);
    transsplit_k<<<dim3(16, 16), 256>>>(W_enc, Wenc2t, H2_, H2_);
    transsplit_k<<<dim3(16, 16), 256>>>(W_dec, Wdec2t, H2_, H2_);
    transsplit_k<<<dim3(4, 48), 256>>>(W_proj, Wproj2t, 3*H2_, E_);
    split_k<<<(BT_*H2_ + 255)/256, 256>>>(dec, dec2, BT_, H2_, 0);
    split_k<<<(B_*L_*H2_ + 255)/256, 256>>>(enc, enc2, B_*L_, H2_, 1);

    // 1) bilinear projections via MMA
    gmma(BT_, H2_, H2_, dec2, 0, Wenc2t, 0, Xe, H2_, 0, 1);
    gmma(BT_, H2_, H2_, dec2, 0, Wdec2t, 0, Xd, H2_, 0, 1);

    // 2) encoder attention scores via batched MMA
    split_k<<<(BT_*H2_ + 255)/256, 256>>>(Xe, Xe2, BT_, H2_, 0);
    gmma(T_, L_, H2_, Xe2, (long long)T_*3*H2_, enc2, (long long)L_*3*H2_,
         att, L_, (long long)T_*L_, B_);

    // 3) intra-temporal + normalize
    temporal_k<<<(B_*(L_/4) + 255)/256, 256>>>(att);
    encnorm_k<<<BT_, 128>>>(att);

    // 4) fused decoder self-attention
    dec_att_k<<<BT_, 256>>>(Xd, dec, s);

    // 5) assemble cat = [h | enc_ctx | dec_ctx]
    copyh_k<<<(BT_*H2_ + 255)/256, 256>>>(dec, cat);
    gemm(T_, H2_, L_, att, L_, (long long)T_*L_,
         enc, H2_, (long long)L_*H2_, 0,
         cat + H2_, 3*H2_, (long long)T_*3*H2_, B_);
    gemm(T_, H2_, T_, s, T_, (long long)T_*T_,
         dec, H2_, (long long)T_*H2_, 0,
         cat + 2*H2_, 3*H2_, (long long)T_*3*H2_, B_);

    // 6) copy gate + embedding projection via MMA
    pgate_k<<<BT_, 256>>>(cat, w_ptr, b_ptr, p);
    split_k<<<(BT_*3*H2_ + 255)/256, 256>>>(cat, cat2, BT_, 3*H2_, 0);
    gmma(BT_, E_, 3*H2_, cat2, 0, Wproj2t, 0, proj, E_, 0, 1);

    // 7) vocab logits via tensor cores (fused exp + row-sum epilogue)
    convA_k<<<(BT_*E_ + 255)/256, 256>>>(proj, A2);
    {
        dim3 grid((V_ + MBN - 1) / MBN, BT_ / MBM);
        vocab_mma_k<<<grid, 256>>>(A2, B2t, logits, rsum);
    }

    // 8) final distribution write + pointer scatter
    final_k<<<dim3((VEXT_/4 + 255)/256, BT_), 256>>>(logits, rsum, p, out);
    scatter_k<<<(BT_*L_ + 255)/256, 256>>>(ev, att, p, out);
}

// round 16
// speedup vs baseline: 1.7051x; 1.1257x over previous
#include <cuda_runtime.h>
#include <cuda_bf16.h>
#include <math.h>

#define B_   32
#define T_   48
#define L_   400
#define H2_  512
#define E_   128
#define V_   50000
#define OOV_ 100
#define VEXT_ 50100
#define BT_  (B_*T_)

// ldmatrix x4: thread t supplies row (t&7) of matrix (t>>3); result distribution
// per matrix: thread t holds (row = t>>2, cols = 2*(t&3)+{0,1}).
#define LDSM4(r0, r1, r2, r3, addr) \
    asm volatile("ldmatrix.sync.aligned.m8n8.x4.shared.b16 {%0,%1,%2,%3}, [%4];" \
        : "=r"(r0), "=r"(r1), "=r"(r2), "=r"(r3) : "r"(addr))

// ---------------- scratch ----------------
__device__ float g_Xe[BT_*H2_];
__device__ float g_Xd[BT_*H2_];
__device__ float g_att[BT_*L_];
__device__ float g_s[BT_*T_];
__device__ float g_cat[BT_*3*H2_];
__device__ float g_p[BT_];
__device__ float g_rsum[BT_];
__device__ float g_logits[(size_t)BT_*V_];
__device__ __nv_bfloat16 g_A2[(size_t)BT_*3*E_];
__device__ __nv_bfloat16 g_B2t[(size_t)V_*3*E_];
__device__ __nv_bfloat16 g_dec2 [(size_t)BT_*3*H2_];
__device__ __nv_bfloat16 g_Xe2  [(size_t)BT_*3*H2_];
__device__ __nv_bfloat16 g_enc2 [(size_t)B_*L_*3*H2_];
__device__ __nv_bfloat16 g_cat2 [(size_t)BT_*9*H2_];
__device__ __nv_bfloat16 g_Wenc2t[(size_t)H2_*3*H2_];
__device__ __nv_bfloat16 g_Wdec2t[(size_t)H2_*3*H2_];
__device__ __nv_bfloat16 g_Wproj2t[(size_t)E_*9*H2_];

__device__ __forceinline__ void split2(float x, __nv_bfloat16& hi, __nv_bfloat16& lo)
{
    hi = __float2bfloat16(x);
    lo = __float2bfloat16(x - __bfloat162float(hi));
}

// ---------------- fp32 GEMM with register prefetch + optional split epilogue -------
#define TM 64
#define TN 64
#define TKK 16

__global__ void gemm_k(int M, int N, int K,
                       const float* __restrict__ A, int lda, long long sA,
                       const float* __restrict__ B, int ldb, long long sB, int transB,
                       float* __restrict__ C, int ldc, long long sC,
                       __nv_bfloat16* __restrict__ D2, int ld2, long long sD2, int Koff)
{
    __shared__ float As[TKK][TM];
    __shared__ float Bs[TKK][TN];
    int bz = blockIdx.z;
    A += (long long)bz * sA;
    B += (long long)bz * sB;
    C += (long long)bz * sC;
    if (D2) D2 += (long long)bz * sD2;
    int m0 = blockIdx.y * TM;
    int n0 = blockIdx.x * TN;
    int tid = threadIdx.x;
    int tx = tid & 15, ty = tid >> 4;
    float acc[4][4] = {};
    float ar[4], br[4];

#pragma unroll
    for (int i = 0; i < 4; i++) {
        int li = tid + 256 * i;
        int m = li & 63, k = li >> 6;
        int gm = m0 + m, gk = k;
        ar[i] = (gm < M && gk < K) ? A[(long long)gm * lda + gk] : 0.f;
    }
#pragma unroll
    for (int i = 0; i < 4; i++) {
        int li = tid + 256 * i;
        int n = li & 63, k = li >> 6;
        int gn = n0 + n, gk = k;
        float v = 0.f;
        if (gn < N && gk < K)
            v = transB ? B[(long long)gn * ldb + gk] : B[(long long)gk * ldb + gn];
        br[i] = v;
    }

    for (int kk = 0; kk < K; kk += TKK) {
#pragma unroll
        for (int i = 0; i < 4; i++) { int li = tid + 256*i; As[li>>6][li&63] = ar[i]; }
#pragma unroll
        for (int i = 0; i < 4; i++) { int li = tid + 256*i; Bs[li>>6][li&63] = br[i]; }
        __syncthreads();

        int kn = kk + TKK;
        if (kn < K) {
#pragma unroll
            for (int i = 0; i < 4; i++) {
                int li = tid + 256 * i;
                int m = li & 63, k = li >> 6;
                int gm = m0 + m, gk = kn + k;
                ar[i] = (gm < M && gk < K) ? A[(long long)gm * lda + gk] : 0.f;
            }
#pragma unroll
            for (int i = 0; i < 4; i++) {
                int li = tid + 256 * i;
                int n = li & 63, k = li >> 6;
                int gn = n0 + n, gk = kn + k;
                float v = 0.f;
                if (gn < N && gk < K)
                    v = transB ? B[(long long)gn * ldb + gk] : B[(long long)gk * ldb + gn];
                br[i] = v;
            }
        }

#pragma unroll
        for (int k = 0; k < TKK; k++) {
            float a0[4], b0[4];
#pragma unroll
            for (int i = 0; i < 4; i++) a0[i] = As[k][ty*4 + i];
#pragma unroll
            for (int j = 0; j < 4; j++) b0[j] = Bs[k][tx*4 + j];
#pragma unroll
            for (int i = 0; i < 4; i++)
#pragma unroll
                for (int j = 0; j < 4; j++)
                    acc[i][j] = fmaf(a0[i], b0[j], acc[i][j]);
        }
        __syncthreads();
    }
#pragma unroll
    for (int i = 0; i < 4; i++) {
        int gm = m0 + ty*4 + i;
        if (gm >= M) continue;
#pragma unroll
        for (int j = 0; j < 4; j++) {
            int gn = n0 + tx*4 + j;
            if (gn < N) {
                C[(long long)gm * ldc + gn] = acc[i][j];
                if (D2) {
                    __nv_bfloat16 hi, lo;
                    split2(acc[i][j], hi, lo);
                    __nv_bfloat16* row = D2 + (long long)gm * ld2;
                    row[gn]          = hi;
                    row[Koff + gn]   = hi;
                    row[2*Koff + gn] = lo;
                }
            }
        }
    }
}

// ============ split conversions ============
// combined: dec -> dec2 (A-mode), enc -> enc2 (B-mode)
__global__ void splitall_k(const float* __restrict__ dec, const float* __restrict__ enc,
                           __nv_bfloat16* __restrict__ dec2, __nv_bfloat16* __restrict__ enc2)
{
    const int t1 = BT_ * H2_;
    const int t2 = B_ * L_ * H2_;
    int idx = blockIdx.x * blockDim.x + threadIdx.x;
    if (idx < t1) {
        int r = idx >> 9, k = idx & 511;
        __nv_bfloat16 hi, lo;
        split2(dec[idx], hi, lo);
        __nv_bfloat16* row = dec2 + (size_t)r * 3 * H2_;
        row[k] = hi; row[H2_ + k] = hi; row[2*H2_ + k] = lo;     // A-mode
    } else if (idx < t1 + t2) {
        int j = idx - t1;
        int r = j >> 9, k = j & 511;
        __nv_bfloat16 hi, lo;
        split2(enc[j], hi, lo);
        __nv_bfloat16* row = enc2 + (size_t)r * 3 * H2_;
        row[k] = hi; row[H2_ + k] = lo; row[2*H2_ + k] = hi;     // B-mode
    }
}

// transpose + split, 32x32 tiles (B-mode)
__global__ void transsplit_k(const float* __restrict__ src, __nv_bfloat16* __restrict__ dst,
                             int K, int N)
{
    __shared__ float sh[32][33];
    int n0 = blockIdx.x * 32;
    int k0 = blockIdx.y * 32;
    int tid = threadIdx.x;
    for (int idx = tid; idx < 32*32; idx += 256) {
        int kk = idx >> 5, nn = idx & 31;
        float v = 0.f;
        if (k0 + kk < K && n0 + nn < N) v = src[(size_t)(k0 + kk) * N + n0 + nn];
        sh[kk][nn] = v;
    }
    __syncthreads();
    for (int idx = tid; idx < 32*32; idx += 256) {
        int nn = idx >> 5, kk = idx & 31;
        if (n0 + nn >= N || k0 + kk >= K) continue;
        __nv_bfloat16 hi, lo;
        split2(sh[kk][nn], hi, lo);
        __nv_bfloat16* row = dst + (size_t)(n0 + nn) * 3 * K;
        row[k0 + kk]       = hi;
        row[K + k0 + kk]   = lo;
        row[2*K + k0 + kk] = hi;
    }
}

// W_vocab transpose+split (B-mode) + rsum zeroing folded into block 0
__global__ void convB_k(const float* __restrict__ Wv, __nv_bfloat16* __restrict__ B2t,
                        float* __restrict__ rsum)
{
    __shared__ float sh[128][65];
    int n0 = blockIdx.x * 64;
    int tid = threadIdx.x;
    if (blockIdx.x == 0)
        for (int i = tid; i < BT_; i += 256) rsum[i] = 0.f;
    for (int idx = tid; idx < 128 * 64; idx += 256) {
        int k = idx >> 6, n = idx & 63;
        float v = 0.f;
        if (n0 + n < V_) v = Wv[(size_t)k * V_ + n0 + n];
        sh[k][n] = v;
    }
    __syncthreads();
    for (int idx = tid; idx < 64 * 128; idx += 256) {
        int n = idx >> 7, k = idx & 127;
        if (n0 + n >= V_) continue;
        __nv_bfloat16 hi, lo;
        split2(sh[k][n], hi, lo);
        __nv_bfloat16* row = B2t + (size_t)(n0 + n) * 384;
        row[k]       = hi;
        row[128 + k] = lo;
        row[256 + k] = hi;
    }
}

// ============ generic batched split-bf16 MMA GEMM (ldmatrix) + optional split out ===
#define GST 40

__global__ void __launch_bounds__(256) gmma_k(
    int M, int N, int NC,
    const __nv_bfloat16* __restrict__ A2, long long sA,
    const __nv_bfloat16* __restrict__ B2, long long sB,
    float* __restrict__ C, int ldc, long long sC,
    __nv_bfloat16* __restrict__ D2, int ld2, int Koff)
{
    __shared__ __nv_bfloat16 As[2][64 * GST];
    __shared__ __nv_bfloat16 Bs[2][64 * GST];
    int bz = blockIdx.z;
    A2 += (long long)bz * sA;
    B2 += (long long)bz * sB;
    C  += (long long)bz * sC;
    long long Ks = (long long)NC * 32;
    int m0 = blockIdx.y * 64;
    int n0 = blockIdx.x * 64;
    int tid  = threadIdx.x;
    int lane = tid & 31, warp = tid >> 5;
    int wm = warp & 1, wn = warp >> 1;
    int group = lane >> 2, tig = lane & 3;

    int lrow = tid >> 2, lcol = (tid & 3) << 3;
    int aguard = (m0 + lrow < M);
    int bguard = (n0 + lrow < N);

    int lm_mat = lane >> 3, lm_r = lane & 7;
    int lm_rowoff = (lm_mat & 1) * 8 + lm_r;
    int lm_koff   = (lm_mat >> 1) * 8;

    float acc[2][2][4];
#pragma unroll
    for (int i = 0; i < 2; i++)
#pragma unroll
        for (int j = 0; j < 2; j++)
#pragma unroll
            for (int q = 0; q < 4; q++) acc[i][j][q] = 0.f;

    uint4 ra = make_uint4(0,0,0,0), rb = make_uint4(0,0,0,0);
    if (aguard) ra = *(const uint4*)(A2 + (size_t)(m0 + lrow) * Ks + lcol);
    if (bguard) rb = *(const uint4*)(B2 + (size_t)(n0 + lrow) * Ks + lcol);
    *(uint4*)(As[0] + lrow * GST + lcol) = ra;
    *(uint4*)(Bs[0] + lrow * GST + lcol) = rb;
    __syncthreads();

    for (int c = 0; c < NC; c++) {
        int buf = c & 1;
        if (c + 1 < NC) {
            long long kn = (long long)(c + 1) * 32;
            if (aguard) ra = *(const uint4*)(A2 + (size_t)(m0 + lrow) * Ks + kn + lcol);
            if (bguard) rb = *(const uint4*)(B2 + (size_t)(n0 + lrow) * Ks + kn + lcol);
        }
        unsigned abase = (unsigned)__cvta_generic_to_shared(As[buf]);
        unsigned bbase = (unsigned)__cvta_generic_to_shared(Bs[buf]);
#pragma unroll
        for (int ks = 0; ks < 32; ks += 16) {
            unsigned af[2][4];
#pragma unroll
            for (int mi = 0; mi < 2; mi++) {
                unsigned aaddr = abase +
                    (unsigned)(((wm*32 + mi*16 + lm_rowoff) * GST + ks + lm_koff) * 2);
                LDSM4(af[mi][0], af[mi][1], af[mi][2], af[mi][3], aaddr);
            }
            unsigned bfr[2][2];
            {
                int bni = lm_mat >> 1, bkh = (lm_mat & 1) * 8;
                unsigned baddr = bbase +
                    (unsigned)(((wn*16 + bni*8 + lm_r) * GST + ks + bkh) * 2);
                LDSM4(bfr[0][0], bfr[0][1], bfr[1][0], bfr[1][1], baddr);
            }
#pragma unroll
            for (int mi = 0; mi < 2; mi++)
#pragma unroll
                for (int ni = 0; ni < 2; ni++) {
                    float* c4 = acc[mi][ni];
                    asm volatile(
                        "mma.sync.aligned.m16n8k16.row.col.f32.bf16.bf16.f32 "
                        "{%0,%1,%2,%3}, {%4,%5,%6,%7}, {%8,%9}, {%0,%1,%2,%3};\n"
                        : "+f"(c4[0]), "+f"(c4[1]), "+f"(c4[2]), "+f"(c4[3])
                        : "r"(af[mi][0]), "r"(af[mi][1]), "r"(af[mi][2]), "r"(af[mi][3]),
                          "r"(bfr[ni][0]), "r"(bfr[ni][1]));
                }
        }
        if (c + 1 < NC) {
            int nb = 1 - buf;
            *(uint4*)(As[nb] + lrow * GST + lcol) = ra;
            *(uint4*)(Bs[nb] + lrow * GST + lcol) = rb;
            __syncthreads();
        }
    }

#pragma unroll
    for (int mi = 0; mi < 2; mi++) {
#pragma unroll
        for (int ni = 0; ni < 2; ni++) {
            int gn = n0 + wn * 16 + ni * 8 + tig * 2;
            if (gn >= N) continue;
            float* c4 = acc[mi][ni];
#pragma unroll
            for (int half = 0; half < 2; half++) {
                int gr = m0 + wm * 32 + mi * 16 + group + half * 8;
                if (gr >= M) continue;
                float v0 = c4[half*2], v1 = c4[half*2 + 1];
                *(float2*)(C + (size_t)gr * ldc + gn) = make_float2(v0, v1);
                if (D2) {
                    __nv_bfloat16 h0, l0, h1, l1;
                    split2(v0, h0, l0);
                    split2(v1, h1, l1);
                    __nv_bfloat16* row = D2 + (size_t)gr * ld2;
                    *(__nv_bfloat162*)(row + gn)          = __nv_bfloat162(h0, h1);
                    *(__nv_bfloat162*)(row + Koff + gn)   = __nv_bfloat162(h0, h1);
                    *(__nv_bfloat162*)(row + 2*Koff + gn) = __nv_bfloat162(l0, l1);
                }
            }
        }
    }
}

// ============ vocab GEMM: 128x128 tile, ldmatrix, fused exp epilogue ============
#define MBM 128
#define MBN 128
#define MKC 32
#define MST 40
#define NCHUNK 12

__global__ void __launch_bounds__(256) vocab_mma_k(
    const __nv_bfloat16* __restrict__ A2,
    const __nv_bfloat16* __restrict__ B2t,
    float* __restrict__ C,
    float* __restrict__ rsum)
{
    __shared__ __nv_bfloat16 As[2][MBM * MST];
    __shared__ __nv_bfloat16 Bs[2][MBN * MST];
    __shared__ float rowsum[MBM];
    int m0 = blockIdx.y * MBM;
    int n0 = blockIdx.x * MBN;
    int tid  = threadIdx.x;
    int lane = tid & 31, warp = tid >> 5;
    int wm = warp & 3, wn = warp >> 2;          // 4(m) x 2(n); warp tile 32x64
    int group = lane >> 2, tig = lane & 3;

    int arow0 = tid >> 2,  ac = (tid & 3) << 3;
    int arow1 = arow0 + 64;
    int brow0 = arow0, brow1 = arow1;
    int bg0 = (n0 + brow0 < V_), bg1 = (n0 + brow1 < V_);

    int lm_mat = lane >> 3, lm_r = lane & 7;
    int lm_rowoff = (lm_mat & 1) * 8 + lm_r;
    int lm_koff   = (lm_mat >> 1) * 8;
    int bni = lm_mat >> 1, bkh = (lm_mat & 1) * 8;

    float acc[2][8][4];
#pragma unroll
    for (int i = 0; i < 2; i++)
#pragma unroll
        for (int j = 0; j < 8; j++)
#pragma unroll
            for (int q = 0; q < 4; q++) acc[i][j][q] = 0.f;

    for (int i = tid; i < MBM; i += 256) rowsum[i] = 0.f;

    uint4 ra0, ra1, rb0, rb1;
    ra0 = *(const uint4*)(A2 + (size_t)(m0 + arow0) * 384 + ac);
    ra1 = *(const uint4*)(A2 + (size_t)(m0 + arow1) * 384 + ac);
    rb0 = make_uint4(0u,0u,0u,0u);
    rb1 = make_uint4(0u,0u,0u,0u);
    if (bg0) rb0 = *(const uint4*)(B2t + (size_t)(n0 + brow0) * 384 + ac);
    if (bg1) rb1 = *(const uint4*)(B2t + (size_t)(n0 + brow1) * 384 + ac);
    *(uint4*)(As[0] + arow0 * MST + ac) = ra0;
    *(uint4*)(As[0] + arow1 * MST + ac) = ra1;
    *(uint4*)(Bs[0] + brow0 * MST + ac) = rb0;
    *(uint4*)(Bs[0] + brow1 * MST + ac) = rb1;
    __syncthreads();

    for (int c = 0; c < NCHUNK; c++) {
        int buf = c & 1;
        int kn = (c + 1) * MKC;
        if (c + 1 < NCHUNK) {
            ra0 = *(const uint4*)(A2 + (size_t)(m0 + arow0) * 384 + kn + ac);
            ra1 = *(const uint4*)(A2 + (size_t)(m0 + arow1) * 384 + kn + ac);
            if (bg0) rb0 = *(const uint4*)(B2t + (size_t)(n0 + brow0) * 384 + kn + ac);
            if (bg1) rb1 = *(const uint4*)(B2t + (size_t)(n0 + brow1) * 384 + kn + ac);
        }
        unsigned abase = (unsigned)__cvta_generic_to_shared(As[buf]);
        unsigned bbase = (unsigned)__cvta_generic_to_shared(Bs[buf]);
#pragma unroll
        for (int ks = 0; ks < MKC; ks += 16) {
            unsigned af[2][4];
#pragma unroll
            for (int mi = 0; mi < 2; mi++) {
                unsigned aaddr = abase +
                    (unsigned)(((wm*32 + mi*16 + lm_rowoff) * MST + ks + lm_koff) * 2);
                LDSM4(af[mi][0], af[mi][1], af[mi][2], af[mi][3], aaddr);
            }
            unsigned bfr[8][2];
#pragma unroll
            for (int j = 0; j < 4; j++) {
                unsigned baddr = bbase +
                    (unsigned)(((wn*64 + j*16 + bni*8 + lm_r) * MST + ks + bkh) * 2);
                LDSM4(bfr[2*j][0], bfr[2*j][1], bfr[2*j+1][0], bfr[2*j+1][1], baddr);
            }
#pragma unroll
            for (int mi = 0; mi < 2; mi++)
#pragma unroll
                for (int ni = 0; ni < 8; ni++) {
                    float* c4 = acc[mi][ni];
                    asm volatile(
                        "mma.sync.aligned.m16n8k16.row.col.f32.bf16.bf16.f32 "
                        "{%0,%1,%2,%3}, {%4,%5,%6,%7}, {%8,%9}, {%0,%1,%2,%3};\n"
                        : "+f"(c4[0]), "+f"(c4[1]), "+f"(c4[2]), "+f"(c4[3])
                        : "r"(af[mi][0]), "r"(af[mi][1]), "r"(af[mi][2]), "r"(af[mi][3]),
                          "r"(bfr[ni][0]), "r"(bfr[ni][1]));
                }
        }
        if (c + 1 < NCHUNK) {
            int nb = 1 - buf;
            *(uint4*)(As[nb] + arow0 * MST + ac) = ra0;
            *(uint4*)(As[nb] + arow1 * MST + ac) = ra1;
            *(uint4*)(Bs[nb] + brow0 * MST + ac) = rb0;
            *(uint4*)(Bs[nb] + brow1 * MST + ac) = rb1;
            __syncthreads();
        }
    }

    // epilogue: exp + store + per-row sums
#pragma unroll
    for (int mi = 0; mi < 2; mi++) {
        int rloc = wm * 32 + mi * 16 + group;
        int r = m0 + rloc;
        float psumA = 0.f, psumB = 0.f;
#pragma unroll
        for (int ni = 0; ni < 8; ni++) {
            int ccol = n0 + wn * 64 + ni * 8 + tig * 2;
            if (ccol < V_) {
                float* c4 = acc[mi][ni];
                float e0 = __expf(c4[0]), e1 = __expf(c4[1]);
                float e2 = __expf(c4[2]), e3 = __expf(c4[3]);
                *(float2*)(C + (size_t)r * V_ + ccol) = make_float2(e0, e1);
                *(float2*)(C + (size_t)(r + 8) * V_ + ccol) = make_float2(e2, e3);
                psumA += e0 + e1;
                psumB += e2 + e3;
            }
        }
        atomicAdd(&rowsum[rloc], psumA);
        atomicAdd(&rowsum[rloc + 8], psumB);
    }
    __syncthreads();
    for (int i = tid; i < MBM; i += 256) atomicAdd(&rsum[m0 + i], rowsum[i]);
}

// ---------------- pointwise / attention kernels (proven) ----------------
__global__ void temporal_k(float* __restrict__ e)
{
    int idx = blockIdx.x * blockDim.x + threadIdx.x;
    if (idx >= B_ * (L_/4)) return;
    int b = idx / (L_/4), l4 = idx % (L_/4);
    float* base = e + (size_t)b * T_ * L_ + l4 * 4;
    float4 acc = make_float4(0.f, 0.f, 0.f, 0.f);
    for (int t = 0; t < T_; t++) {
        float4 x = *(float4*)(base + (size_t)t * L_);
        float4 ex;
        ex.x = __expf(x.x); ex.y = __expf(x.y); ex.z = __expf(x.z); ex.w = __expf(x.w);
        float4 o;
        if (t == 0) o = ex;
        else {
            o.x = ex.x / acc.x; o.y = ex.y / acc.y;
            o.z = ex.z / acc.z; o.w = ex.w / acc.w;
        }
        *(float4*)(base + (size_t)t * L_) = o;
        acc.x += ex.x; acc.y += ex.y; acc.z += ex.z; acc.w += ex.w;
    }
}

__global__ void encnorm_k(float* __restrict__ att)
{
    int r = blockIdx.x;
    float* row = att + (size_t)r * L_;
    float acc = 0.f;
    for (int i = threadIdx.x; i < L_; i += 128) acc += row[i];
    __shared__ float sh[128];
    sh[threadIdx.x] = acc;
    __syncthreads();
    for (int st = 64; st > 0; st >>= 1) {
        if (threadIdx.x < st) sh[threadIdx.x] += sh[threadIdx.x + st];
        __syncthreads();
    }
    float inv = 1.f / sh[0];
    for (int i = threadIdx.x; i < L_; i += 128) row[i] *= inv;
}

__global__ void __launch_bounds__(256) dec_att_k(
    const float* __restrict__ Xd, const float* __restrict__ dec,
    float* __restrict__ datt)
{
    int r = blockIdx.x;
    int b = r / T_, t = r % T_;
    int tid = threadIdx.x;
    float* orow = datt + (size_t)r * T_;
    if (t == 0) {
        if (tid < T_) orow[tid] = 0.f;
        return;
    }
    __shared__ float4 xs[H2_/4];
    __shared__ float sc[T_];
    for (int i = tid; i < H2_/4; i += 256)
        xs[i] = *(const float4*)(Xd + (size_t)r * H2_ + i*4);
    __syncthreads();
    int warp = tid >> 5, lane = tid & 31;
    for (int j = warp; j < t; j += 8) {
        const float4* drow = (const float4*)(dec + ((size_t)b * T_ + j) * H2_);
        float a = 0.f;
#pragma unroll
        for (int i = 0; i < H2_/128; i++) {
            float4 x = xs[lane + 32*i];
            float4 d = drow[lane + 32*i];
            a += x.x*d.x + x.y*d.y + x.z*d.z + x.w*d.w;
        }
#pragma unroll
        for (int o = 16; o > 0; o >>= 1) a += __shfl_xor_sync(0xffffffffu, a, o);
        if (lane == 0) sc[j] = a;
    }
    __syncthreads();
    if (warp == 0) {
        float v1 = (lane < t) ? sc[lane] : -1e30f;
        float v2 = (lane + 32 < t) ? sc[lane + 32] : -1e30f;
        float m = fmaxf(v1, v2);
#pragma unroll
        for (int o = 16; o > 0; o >>= 1) m = fmaxf(m, __shfl_xor_sync(0xffffffffu, m, o));
        float e1 = (lane < t) ? __expf(v1 - m) : 0.f;
        float e2 = (lane + 32 < t) ? __expf(v2 - m) : 0.f;
        float s = e1 + e2;
#pragma unroll
        for (int o = 16; o > 0; o >>= 1) s += __shfl_xor_sync(0xffffffffu, s, o);
        float inv = 1.f / s;
        if (lane < T_) orow[lane] = e1 * inv;
        if (lane + 32 < T_) orow[lane + 32] = e2 * inv;
    }
}

// copy h into cat[:,0:H2] AND its split into cat2 cols [0,512)
__global__ void copyh_k(const float* __restrict__ dec, float* __restrict__ cat,
                        __nv_bfloat16* __restrict__ cat2)
{
    int idx = blockIdx.x * blockDim.x + threadIdx.x;
    if (idx >= BT_ * H2_) return;
    int r = idx >> 9, h = idx & 511;
    float x = dec[idx];
    cat[(size_t)r * (3*H2_) + h] = x;
    __nv_bfloat16 hi, lo;
    split2(x, hi, lo);
    __nv_bfloat16* row = cat2 + (size_t)r * (9*H2_);
    row[h]            = hi;
    row[3*H2_ + h]    = hi;
    row[6*H2_ + h]    = lo;
}

__global__ void pgate_k(const float* __restrict__ cat, const float* __restrict__ w,
                        const float* __restrict__ bb, float* __restrict__ p)
{
    int r = blockIdx.x;
    const float* row = cat + (size_t)r * (3*H2_);
    float acc = 0.f;
    for (int i = threadIdx.x; i < 3*H2_; i += 256) acc += row[i] * w[i];
    __shared__ float sh[256];
    sh[threadIdx.x] = acc;
    __syncthreads();
    for (int st = 128; st > 0; st >>= 1) {
        if (threadIdx.x < st) sh[threadIdx.x] += sh[threadIdx.x + st];
        __syncthreads();
    }
    if (threadIdx.x == 0) p[r] = 1.f / (1.f + __expf(-(sh[0] + bb[0])));
}

__global__ void final_k(const float* __restrict__ explogits,
                        const float* __restrict__ rsum, const float* __restrict__ p,
                        float* __restrict__ out)
{
    int r = blockIdx.y;
    int v4 = blockIdx.x * blockDim.x + threadIdx.x;
    if (v4 >= VEXT_/4) return;
    float4 o = make_float4(0.f, 0.f, 0.f, 0.f);
    if (v4 < V_/4) {
        float sc = (1.f - p[r]) / rsum[r];
        float4 x = *(const float4*)(explogits + (size_t)r * V_ + v4*4);
        o.x = sc * x.x; o.y = sc * x.y; o.z = sc * x.z; o.w = sc * x.w;
    }
    *(float4*)(out + (size_t)r * VEXT_ + v4*4) = o;
}

__global__ void scatter_k(const int* __restrict__ ev, const float* __restrict__ att,
                          const float* __restrict__ p, float* __restrict__ out)
{
    int idx = blockIdx.x * blockDim.x + threadIdx.x;
    if (idx >= BT_ * L_) return;
    int l = idx % L_;
    int r = idx / L_;
    int b = r / T_;
    float val = p[r] * att[idx];
    atomicAdd(&out[(size_t)r * VEXT_ + ev[b * L_ + l]], val);
}

// ---------------- host orchestration ----------------
static void gemm(int M, int N, int K,
                 const float* A, int lda, long long sA,
                 const float* B, int ldb, long long sB, int transB,
                 float* C, int ldc, long long sC, int batch,
                 __nv_bfloat16* D2, int ld2, long long sD2, int Koff)
{
    dim3 grid((N + TN - 1) / TN, (M + TM - 1) / TM, batch);
    gemm_k<<<grid, 256>>>(M, N, K, A, lda, sA, B, ldb, sB, transB, C, ldc, sC,
                          D2, ld2, sD2, Koff);
}

static void gmma(int M, int N, int K,
                 const __nv_bfloat16* A2, long long sA,
                 const __nv_bfloat16* B2, long long sB,
                 float* C, int ldc, long long sC, int batch,
                 __nv_bfloat16* D2, int ld2, int Koff)
{
    dim3 grid((N + 63) / 64, (M + 63) / 64, batch);
    gmma_k<<<grid, 256>>>(M, N, (3 * K) / 32, A2, sA, B2, sB, C, ldc, sC,
                          D2, ld2, Koff);
}

extern "C" void kernel_launch(void* const* d_in, const int* in_sizes, int n_in,
                              void* d_out, int out_size)
{
    const float* dec     = (const float*)d_in[0];
    const float* enc     = (const float*)d_in[1];
    const float* W_enc   = (const float*)d_in[2];
    const float* W_dec   = (const float*)d_in[3];
    const float* W_proj  = (const float*)d_in[4];
    const float* W_vocab = (const float*)d_in[5];
    const float* w_ptr   = (const float*)d_in[6];
    const float* b_ptr   = (const float*)d_in[7];
    const int*   ev      = (const int*)d_in[8];
    float* out = (float*)d_out;

    float *Xe, *Xd, *att, *s, *cat, *p, *rsum, *logits;
    __nv_bfloat16 *A2, *B2t, *dec2, *Xe2, *enc2, *cat2, *Wenc2t, *Wdec2t, *Wproj2t;
    cudaGetSymbolAddress((void**)&Xe,     g_Xe);
    cudaGetSymbolAddress((void**)&Xd,     g_Xd);
    cudaGetSymbolAddress((void**)&att,    g_att);
    cudaGetSymbolAddress((void**)&s,      g_s);
    cudaGetSymbolAddress((void**)&cat,    g_cat);
    cudaGetSymbolAddress((void**)&p,      g_p);
    cudaGetSymbolAddress((void**)&rsum,   g_rsum);
    cudaGetSymbolAddress((void**)&logits, g_logits);
    cudaGetSymbolAddress((void**)&A2,     g_A2);
    cudaGetSymbolAddress((void**)&B2t,    g_B2t);
    cudaGetSymbolAddress((void**)&dec2,   g_dec2);
    cudaGetSymbolAddress((void**)&Xe2,    g_Xe2);
    cudaGetSymbolAddress((void**)&enc2,   g_enc2);
    cudaGetSymbolAddress((void**)&cat2,   g_cat2);
    cudaGetSymbolAddress((void**)&Wenc2t, g_Wenc2t);
    cudaGetSymbolAddress((void**)&Wdec2t, g_Wdec2t);
    cudaGetSymbolAddress((void**)&Wproj2t,g_Wproj2t);

    // 0) conversions (rsum zeroing folded into convB)
    convB_k<<<(V_ + 63) / 64, 256>>>(W_vocab, B2t, rsum);
    transsplit_k<<<dim3(16, 16), 256>>>(W_enc, Wenc2t, H2_, H2_);
    transsplit_k<<<dim3(16, 16), 256>>>(W_dec, Wdec2t, H2_, H2_);
    transsplit_k<<<dim3(4, 48), 256>>>(W_proj, Wproj2t, 3*H2_, E_);
    splitall_k<<<((BT_ + B_*L_)*H2_ + 255)/256, 256>>>(dec, enc, dec2, enc2);

    // 1) bilinear projections via MMA; Xe epilogue emits Xe2 split directly
    gmma(BT_, H2_, H2_, dec2, 0, Wenc2t, 0, Xe, H2_, 0, 1, Xe2, 3*H2_, H2_);
    gmma(BT_, H2_, H2_, dec2, 0, Wdec2t, 0, Xd, H2_, 0, 1, nullptr, 0, 0);

    // 2) encoder attention scores via batched MMA
    gmma(T_, L_, H2_, Xe2, (long long)T_*3*H2_, enc2, (long long)L_*3*H2_,
         att, L_, (long long)T_*L_, B_, nullptr, 0, 0);

    // 3) intra-temporal + normalize
    temporal_k<<<(B_*(L_/4) + 255)/256, 256>>>(att);
    encnorm_k<<<BT_, 128>>>(att);

    // 4) fused decoder self-attention
    dec_att_k<<<BT_, 256>>>(Xd, dec, s);

    // 5) assemble cat (+ cat2 split slices in epilogues)
    copyh_k<<<(BT_*H2_ + 255)/256, 256>>>(dec, cat, cat2);
    gemm(T_, H2_, L_, att, L_, (long long)T_*L_,
         enc, H2_, (long long)L_*H2_, 0,
         cat + H2_, 3*H2_, (long long)T_*3*H2_, B_,
         cat2 + H2_, 9*H2_, (long long)T_*9*H2_, 3*H2_);
    gemm(T_, H2_, T_, s, T_, (long long)T_*T_,
         dec, H2_, (long long)T_*H2_, 0,
         cat + 2*H2_, 3*H2_, (long long)T_*3*H2_, B_,
         cat2 + 2*H2_, 9*H2_, (long long)T_*9*H2_, 3*H2_);

    // 6) copy gate + embedding projection (epilogue emits A2 split directly)
    pgate_k<<<BT_, 256>>>(cat, w_ptr, b_ptr, p);
    {
        float* projdummy = Xe;   // reuse Xe as f32 landing (no longer needed)
        gmma(BT_, E_, 3*H2_, cat2, 0, Wproj2t, 0, projdummy, E_, 0, 1, A2, 3*E_, E_);
    }

    // 7) vocab logits (128x128 tile, fused exp + row-sum epilogue)
    {
        dim3 grid((V_ + MBN - 1) / MBN, BT_ / MBM);
        vocab_mma_k<<<grid, 256>>>(A2, B2t, logits, rsum);
    }

    // 8) final distribution write + pointer scatter
    final_k<<<dim3((VEXT_/4 + 255)/256, BT_), 256>>>(logits, rsum, p, out);
    scatter_k<<<(BT_*L_ + 255)/256, 256>>>(ev, att, p, out);
}